// round 12
// baseline (speedup 1.0000x reference)
#include <cuda_runtime.h>
#include <cuda_fp16.h>
#include <cstdint>

#define BB   512
#define CC   512
#define EE   128
#define HWW  240
#define GATES 1536   // 3*C
#define KX    640    // C+E

// -------- scratch (static device arrays; no allocation allowed) -----------
// partials: index [gemm*2 + split][B*GATES]; gemm 0 = gi, 1 = gh
__device__ float g_part[4][BB * GATES];
__device__ float g_alpha[BB * HWW];

__device__ __half g_xh [BB * KX];     // fp16 x = [context, emb]
__device__ __half g_hh [BB * CC];     // fp16 prev_hidden
__device__ __half g_wih[GATES * KX];  // fp16 w_ih
__device__ __half g_whh[GATES * CC];  // fp16 w_hh

__device__ __forceinline__ float tanh_fast(float x) {
    float y; asm("tanh.approx.f32 %0, %1;" : "=f"(y) : "f"(x)); return y;
}
__device__ __forceinline__ float sigmoid_fast(float x) {
    return 0.5f * tanh_fast(0.5f * x) + 0.5f;
}

// ---------------------------------------------------------------------------
// split3: fp32 -> fp16 for w_ih, w_hh, prev_hidden; float4-wide.
// ---------------------------------------------------------------------------
#define N1 (GATES * KX)
#define N2 (GATES * CC)
#define N3 (BB * CC)

__global__ __launch_bounds__(256) void split3_kernel(
    const float* __restrict__ w_ih, const float* __restrict__ w_hh,
    const float* __restrict__ h)
{
    int i = blockIdx.x * 256 + threadIdx.x;
    const float* src; __half* dst; int off;
    if (i < N1 / 4)            { src = w_ih; dst = g_wih; off = i; }
    else if (i < (N1 + N2) / 4){ src = w_hh; dst = g_whh; off = i - N1 / 4; }
    else                       { src = h;    dst = g_hh;  off = i - (N1 + N2) / 4; }

    float4 v = reinterpret_cast<const float4*>(src)[off];
    __half2 p0 = __floats2half2_rn(v.x, v.y);
    __half2 p1 = __floats2half2_rn(v.z, v.w);
    uint2 u = {*(uint32_t*)&p0, *(uint32_t*)&p1};
    reinterpret_cast<uint2*>(dst)[off] = u;
}

// ---------------------------------------------------------------------------
// Kernel 1: score + softmax. One block per b, 512 threads.
// ---------------------------------------------------------------------------
__global__ __launch_bounds__(512) void score_kernel(
    const float* __restrict__ ph,
    const float* __restrict__ cf,
    const float* __restrict__ emb,
    const float* __restrict__ sw,
    float* __restrict__ alphaT)
{
    const int b   = blockIdx.x;
    const int tid = threadIdx.x;

    __shared__ __align__(16) float s_ph[CC];
    __shared__ __align__(16) float s_sw[CC];
    __shared__ __align__(16) float s_part[16][HWW];
    __shared__ float s_red[16];
    __shared__ float s_red2[16];

    for (int i = tid; i < CC; i += 512) {
        s_ph[i] = ph[(size_t)b * CC + i];
        s_sw[i] = sw[i];
    }
    __syncthreads();

    const int g = tid >> 5;
    const int t = tid & 31;
    if (t < 30) {
        const float4* p4 = reinterpret_cast<const float4*>(
            cf + ((size_t)b * CC + g * 32) * HWW) + 2 * t;
        float4 a0 = make_float4(0.f, 0.f, 0.f, 0.f);
        float4 a1 = make_float4(0.f, 0.f, 0.f, 0.f);
        #pragma unroll 4
        for (int c = 0; c < 32; ++c) {
            float4 v0 = __ldcs(p4 + (size_t)c * 60);
            float4 v1 = __ldcs(p4 + (size_t)c * 60 + 1);
            float hp = s_ph[g * 32 + c];
            float w  = s_sw[g * 32 + c];
            a0.x += tanh_fast(v0.x + hp) * w;
            a0.y += tanh_fast(v0.y + hp) * w;
            a0.z += tanh_fast(v0.z + hp) * w;
            a0.w += tanh_fast(v0.w + hp) * w;
            a1.x += tanh_fast(v1.x + hp) * w;
            a1.y += tanh_fast(v1.y + hp) * w;
            a1.z += tanh_fast(v1.z + hp) * w;
            a1.w += tanh_fast(v1.w + hp) * w;
        }
        *reinterpret_cast<float4*>(&s_part[g][8 * t])     = a0;
        *reinterpret_cast<float4*>(&s_part[g][8 * t + 4]) = a1;
    }
    __syncthreads();

    float eval = 0.f;
    if (tid < HWW) {
        #pragma unroll
        for (int gg = 0; gg < 16; ++gg) eval += s_part[gg][tid];
    }
    const int lane = tid & 31, wid = tid >> 5;

    float v = (tid < HWW) ? eval : -3.0e38f;
    #pragma unroll
    for (int o = 16; o; o >>= 1) v = fmaxf(v, __shfl_xor_sync(0xffffffffu, v, o));
    if (lane == 0) s_red[wid] = v;
    __syncthreads();
    float m = s_red[0];
    #pragma unroll
    for (int i = 1; i < 16; ++i) m = fmaxf(m, s_red[i]);

    float e = (tid < HWW) ? __expf(eval - m) : 0.f;
    float sv = e;
    #pragma unroll
    for (int o = 16; o; o >>= 1) sv += __shfl_xor_sync(0xffffffffu, sv, o);
    if (lane == 0) s_red2[wid] = sv;
    __syncthreads();
    float tot = 0.f;
    #pragma unroll
    for (int i = 0; i < 16; ++i) tot += s_red2[i];

    if (tid < HWW) {
        const float alpha = e / tot;
        g_alpha[(size_t)b * HWW + tid] = alpha;
        alphaT[(size_t)tid * BB + b] = alpha;
    }
    if (tid < EE) {
        g_xh[(size_t)b * KX + CC + tid] = __float2half_rn(emb[(size_t)b * EE + tid]);
    }
}

// ---------------------------------------------------------------------------
// Kernel 2: context GEMV. grid (8, B), 256 threads; warp per channel row.
// Two-phase: all loads+FMA first (deep MLP), shuffle reductions deferred.
// ---------------------------------------------------------------------------
__global__ __launch_bounds__(256) void ctx_kernel(const float* __restrict__ cfo)
{
    const int b  = blockIdx.y;
    const int c0 = blockIdx.x * 64;
    const int tid = threadIdx.x;
    const int lane = tid & 31, w = tid >> 5;

    __shared__ __align__(16) float s_alpha[HWW];
    if (tid < HWW) s_alpha[tid] = g_alpha[(size_t)b * HWW + tid];
    __syncthreads();

    const float4* a4 = reinterpret_cast<const float4*>(s_alpha);
    float4 aa = a4[lane];
    float4 a2 = (lane < 28) ? a4[lane + 32] : make_float4(0.f, 0.f, 0.f, 0.f);
    const bool tail = (lane < 28);

    const float4* base = reinterpret_cast<const float4*>(
        cfo + ((size_t)b * CC + c0 + w * 8) * HWW);

    float s[8];
    #pragma unroll
    for (int r = 0; r < 8; ++r) {
        const float4* rp = base + (size_t)r * 60;
        float4 vv = __ldcs(rp + lane);
        float4 v2 = tail ? __ldcs(rp + lane + 32) : make_float4(0.f, 0.f, 0.f, 0.f);
        s[r] = vv.x * aa.x + vv.y * aa.y + vv.z * aa.z + vv.w * aa.w
             + v2.x * a2.x + v2.y * a2.y + v2.z * a2.z + v2.w * a2.w;
    }

    #pragma unroll
    for (int r = 0; r < 8; ++r) {
        #pragma unroll
        for (int o = 16; o; o >>= 1) s[r] += __shfl_xor_sync(0xffffffffu, s[r], o);
    }
    if (lane < 8) {
        // lane r writes s[r] — gather via one more shuffle round trip
    }
    if (lane == 0) {
        #pragma unroll
        for (int r = 0; r < 8; ++r)
            g_xh[(size_t)b * KX + c0 + w * 8 + r] = __float2half_rn(s[r]);
    }
}

// ---------------------------------------------------------------------------
// Kernel 3: gate GEMMs, fp16 MMA, split-K=2, chunk K=64, cp.async double buf.
// Tile 64(M) x 64(N). grid (24, 8, 4): z&1 = gemm, z>>1 = split.
// ---------------------------------------------------------------------------
#define ASTR 72   // fp16 row stride: 144 bytes (odd 16B multiple, LDSM conflict-free)

__device__ __forceinline__ void mma16816(float* c, const uint32_t* a, const uint32_t* b) {
    asm volatile(
        "mma.sync.aligned.m16n8k16.row.col.f32.f16.f16.f32 "
        "{%0,%1,%2,%3}, {%4,%5,%6,%7}, {%8,%9}, {%0,%1,%2,%3};"
        : "+f"(c[0]), "+f"(c[1]), "+f"(c[2]), "+f"(c[3])
        : "r"(a[0]), "r"(a[1]), "r"(a[2]), "r"(a[3]),
          "r"(b[0]), "r"(b[1]));
}
__device__ __forceinline__ void ldsm4(uint32_t* r, const __half* p) {
    uint32_t a = (uint32_t)__cvta_generic_to_shared(p);
    asm volatile("ldmatrix.sync.aligned.m8n8.x4.shared.b16 {%0,%1,%2,%3}, [%4];"
                 : "=r"(r[0]), "=r"(r[1]), "=r"(r[2]), "=r"(r[3]) : "r"(a));
}
__device__ __forceinline__ void cpasync16(uint32_t dst, const void* src) {
    asm volatile("cp.async.cg.shared.global [%0], [%1], 16;" :: "r"(dst), "l"(src));
}

__global__ __launch_bounds__(128) void gemm_gates()
{
    const int z      = blockIdx.z;
    const int gemmi  = z & 1;       // 0: gi (K=640), 1: gh (K=512)
    const int split  = z >> 1;      // 0..1

    const __half* A = gemmi ? g_hh  : g_xh;
    const __half* B = gemmi ? g_whh : g_wih;
    float* outp = g_part[gemmi * 2 + split];
    const int K    = gemmi ? CC : KX;
    const int Kq   = K >> 1;        // 320 or 256
    const int koff = split * Kq;
    const int T    = Kq / 64;       // 5 or 4 chunks

    __shared__ __align__(16) __half sA[2][64 * ASTR];
    __shared__ __align__(16) __half sB[2][64 * ASTR];

    const int tid  = threadIdx.x;
    const int lane = tid & 31;
    const int wrp  = tid >> 5;
    const int warp_m = wrp >> 1;
    const int warp_n = wrp & 1;
    const int gID = lane >> 2;
    const int tig = lane & 3;
    const int m0 = blockIdx.y * 64;
    const int n0 = blockIdx.x * 64;

    const int a_rowl = lane & 15;
    const int a_kh   = (lane >> 4) * 8;
    const int b_rowl = ((lane >> 4) * 8) + (lane & 7);
    const int b_kh   = ((lane >> 3) & 1) * 8;

    float acc[2][4][4];
    #pragma unroll
    for (int i = 0; i < 2; ++i)
        #pragma unroll
        for (int j = 0; j < 4; ++j)
            #pragma unroll
            for (int k = 0; k < 4; ++k) acc[i][j][k] = 0.f;

    // chunk = 64 rows x 64 halves (128 B/row): 512 x 16B units; 4 per thread per array
    auto load_stage = [&](int s, int kt) {
        const size_t kbase = (size_t)koff + kt * 64;
        #pragma unroll
        for (int j = 0; j < 4; ++j) {
            int u = tid + 128 * j;
            int row = u >> 3;
            int seg = (u & 7) * 8;
            size_t ga = (size_t)(m0 + row) * K + kbase + seg;
            size_t gb = (size_t)(n0 + row) * K + kbase + seg;
            int so = row * ASTR + seg;
            cpasync16((uint32_t)__cvta_generic_to_shared(&sA[s][so]), A + ga);
            cpasync16((uint32_t)__cvta_generic_to_shared(&sB[s][so]), B + gb);
        }
        asm volatile("cp.async.commit_group;");
    };

    load_stage(0, 0);
    load_stage(1, 1);

    for (int t = 0; t < T; ++t) {
        if (t + 1 < T) { asm volatile("cp.async.wait_group 1;"); }
        else           { asm volatile("cp.async.wait_group 0;"); }
        __syncthreads();

        const int st = t & 1;
        #pragma unroll
        for (int k8 = 0; k8 < 4; ++k8) {
            const int kb = k8 * 16;
            uint32_t ah[2][4];
            #pragma unroll
            for (int m2 = 0; m2 < 2; ++m2) {
                const int r = warp_m * 32 + m2 * 16 + a_rowl;
                ldsm4(ah[m2], &sA[st][r * ASTR + kb + a_kh]);
            }
            uint32_t bh[4][2];
            #pragma unroll
            for (int p = 0; p < 2; ++p) {
                const int r = warp_n * 32 + p * 16 + b_rowl;
                uint32_t t4[4];
                ldsm4(t4, &sB[st][r * ASTR + kb + b_kh]);
                bh[2 * p][0] = t4[0]; bh[2 * p][1] = t4[1];
                bh[2 * p + 1][0] = t4[2]; bh[2 * p + 1][1] = t4[3];
            }
            #pragma unroll
            for (int m2 = 0; m2 < 2; ++m2)
                #pragma unroll
                for (int n4 = 0; n4 < 4; ++n4)
                    mma16816(acc[m2][n4], ah[m2], bh[n4]);
        }
        __syncthreads();
        if (t + 2 < T) load_stage(st, t + 2);
    }

    #pragma unroll
    for (int m2 = 0; m2 < 2; ++m2) {
        #pragma unroll
        for (int n4 = 0; n4 < 4; ++n4) {
            int r = m0 + warp_m * 32 + m2 * 16 + gID;
            int cb = n0 + warp_n * 32 + n4 * 8 + tig * 2;
            float2 o0 = {acc[m2][n4][0], acc[m2][n4][1]};
            float2 o1 = {acc[m2][n4][2], acc[m2][n4][3]};
            *reinterpret_cast<float2*>(outp + (size_t)r * GATES + cb) = o0;
            *reinterpret_cast<float2*>(outp + (size_t)(r + 8) * GATES + cb) = o1;
        }
    }
}

// ---------------------------------------------------------------------------
// Kernel 4: GRU combine; sums 2 split-K partials per gemm plus biases.
// ---------------------------------------------------------------------------
__global__ __launch_bounds__(256) void gru_kernel(
    const float* __restrict__ h, const float* __restrict__ b_ih,
    const float* __restrict__ b_hh, float* __restrict__ out)
{
    const int i4 = blockIdx.x * 256 + threadIdx.x;
    const int b = i4 >> 7;
    const int c4 = i4 & 127;
    const size_t row = (size_t)b * GATES;

    float4 gi_r, gi_z, gi_n, gh_r, gh_z, gh_n;
    {
        const float4* bi = reinterpret_cast<const float4*>(b_ih) + c4;
        const float4* bh = reinterpret_cast<const float4*>(b_hh) + c4;
        gi_r = bi[0]; gi_z = bi[128]; gi_n = bi[256];
        gh_r = bh[0]; gh_z = bh[128]; gh_n = bh[256];
    }
    #pragma unroll
    for (int s = 0; s < 2; ++s) {
        const float4* pi = reinterpret_cast<const float4*>(g_part[s]     + row) + c4;
        const float4* pg = reinterpret_cast<const float4*>(g_part[2 + s] + row) + c4;
        float4 a = pi[0], bq = pi[128], cq = pi[256];
        float4 d = pg[0], e = pg[128],  f = pg[256];
        gi_r.x += a.x; gi_r.y += a.y; gi_r.z += a.z; gi_r.w += a.w;
        gi_z.x += bq.x; gi_z.y += bq.y; gi_z.z += bq.z; gi_z.w += bq.w;
        gi_n.x += cq.x; gi_n.y += cq.y; gi_n.z += cq.z; gi_n.w += cq.w;
        gh_r.x += d.x; gh_r.y += d.y; gh_r.z += d.z; gh_r.w += d.w;
        gh_z.x += e.x; gh_z.y += e.y; gh_z.z += e.z; gh_z.w += e.w;
        gh_n.x += f.x; gh_n.y += f.y; gh_n.z += f.z; gh_n.w += f.w;
    }

    float4 hv = reinterpret_cast<const float4*>(h)[i4];
    float4 o;
    {
        float r = sigmoid_fast(gi_r.x + gh_r.x), zz = sigmoid_fast(gi_z.x + gh_z.x);
        float n = tanh_fast(gi_n.x + r * gh_n.x);
        o.x = (1.f - zz) * n + zz * hv.x;
    }
    {
        float r = sigmoid_fast(gi_r.y + gh_r.y), zz = sigmoid_fast(gi_z.y + gh_z.y);
        float n = tanh_fast(gi_n.y + r * gh_n.y);
        o.y = (1.f - zz) * n + zz * hv.y;
    }
    {
        float r = sigmoid_fast(gi_r.z + gh_r.z), zz = sigmoid_fast(gi_z.z + gh_z.z);
        float n = tanh_fast(gi_n.z + r * gh_n.z);
        o.z = (1.f - zz) * n + zz * hv.z;
    }
    {
        float r = sigmoid_fast(gi_r.w + gh_r.w), zz = sigmoid_fast(gi_z.w + gh_z.w);
        float n = tanh_fast(gi_n.w + r * gh_n.w);
        o.w = (1.f - zz) * n + zz * hv.w;
    }
    reinterpret_cast<float4*>(out)[i4] = o;
}

// ---------------------------------------------------------------------------
extern "C" void kernel_launch(void* const* d_in, const int* in_sizes, int n_in,
                              void* d_out, int out_size) {
    const float* prev_hidden       = (const float*)d_in[0];
    const float* conv_feats        = (const float*)d_in[1];
    const float* conv_feats_origin = (const float*)d_in[2];
    const float* cur_embeddings    = (const float*)d_in[3];
    const float* score_w           = (const float*)d_in[4];
    const float* w_ih              = (const float*)d_in[5];
    const float* w_hh              = (const float*)d_in[6];
    const float* b_ih              = (const float*)d_in[7];
    const float* b_hh              = (const float*)d_in[8];

    float* out        = (float*)d_out;
    float* out_hidden = out;                      // [B, C]
    float* out_alphaT = out + (size_t)BB * CC;    // [HW, B]

    split3_kernel<<<(N1 + N2 + N3) / 1024, 256>>>(w_ih, w_hh, prev_hidden);

    score_kernel<<<BB, 512>>>(prev_hidden, conv_feats, cur_embeddings,
                              score_w, out_alphaT);

    dim3 gc(CC / 64, BB);                         // (8, 512)
    ctx_kernel<<<gc, 256>>>(conv_feats_origin);

    dim3 g(GATES / 64, BB / 64, 4);               // (24, 8, 4) = 768 CTAs
    gemm_gates<<<g, 128>>>();

    gru_kernel<<<(BB * CC) / 1024, 256>>>(prev_hidden, b_ih, b_hh, out_hidden);
}

// round 13
// speedup vs baseline: 1.1165x; 1.1165x over previous
#include <cuda_runtime.h>
#include <cuda_fp16.h>
#include <cstdint>

#define BB   512
#define CC   512
#define EE   128
#define HWW  240
#define GATES 1536   // 3*C
#define KX    640    // C+E

// -------- scratch (static device arrays; no allocation allowed) -----------
// partials: index [gemm*4 + split][B*GATES]; gemm 0 = gi, 1 = gh
__device__ float g_part[8][BB * GATES];
__device__ float g_alpha[BB * HWW];

__device__ __half g_xh [BB * KX];     // fp16 x = [context, emb]
__device__ __half g_hh [BB * CC];     // fp16 prev_hidden
__device__ __half g_wih[GATES * KX];  // fp16 w_ih
__device__ __half g_whh[GATES * CC];  // fp16 w_hh

__device__ __forceinline__ float tanh_fast(float x) {
    float y; asm("tanh.approx.f32 %0, %1;" : "=f"(y) : "f"(x)); return y;
}
__device__ __forceinline__ float sigmoid_fast(float x) {
    return 0.5f * tanh_fast(0.5f * x) + 0.5f;
}

// ---------------------------------------------------------------------------
// split3: fp32 -> fp16 for w_ih, w_hh, prev_hidden; float4-wide.
// ---------------------------------------------------------------------------
#define N1 (GATES * KX)
#define N2 (GATES * CC)
#define N3 (BB * CC)

__global__ __launch_bounds__(256) void split3_kernel(
    const float* __restrict__ w_ih, const float* __restrict__ w_hh,
    const float* __restrict__ h)
{
    int i = blockIdx.x * 256 + threadIdx.x;
    const float* src; __half* dst; int off;
    if (i < N1 / 4)            { src = w_ih; dst = g_wih; off = i; }
    else if (i < (N1 + N2) / 4){ src = w_hh; dst = g_whh; off = i - N1 / 4; }
    else                       { src = h;    dst = g_hh;  off = i - (N1 + N2) / 4; }

    float4 v = reinterpret_cast<const float4*>(src)[off];
    __half2 p0 = __floats2half2_rn(v.x, v.y);
    __half2 p1 = __floats2half2_rn(v.z, v.w);
    uint2 u = {*(uint32_t*)&p0, *(uint32_t*)&p1};
    reinterpret_cast<uint2*>(dst)[off] = u;
}

// ---------------------------------------------------------------------------
// Kernel 1: score + softmax. One block per b, 512 threads.
// ---------------------------------------------------------------------------
__global__ __launch_bounds__(512) void score_kernel(
    const float* __restrict__ ph,
    const float* __restrict__ cf,
    const float* __restrict__ emb,
    const float* __restrict__ sw,
    float* __restrict__ alphaT)
{
    const int b   = blockIdx.x;
    const int tid = threadIdx.x;

    __shared__ __align__(16) float s_ph[CC];
    __shared__ __align__(16) float s_sw[CC];
    __shared__ __align__(16) float s_part[16][HWW];
    __shared__ float s_red[16];
    __shared__ float s_red2[16];

    for (int i = tid; i < CC; i += 512) {
        s_ph[i] = ph[(size_t)b * CC + i];
        s_sw[i] = sw[i];
    }
    __syncthreads();

    const int g = tid >> 5;
    const int t = tid & 31;
    if (t < 30) {
        const float4* p4 = reinterpret_cast<const float4*>(
            cf + ((size_t)b * CC + g * 32) * HWW) + 2 * t;
        float4 a0 = make_float4(0.f, 0.f, 0.f, 0.f);
        float4 a1 = make_float4(0.f, 0.f, 0.f, 0.f);
        #pragma unroll 4
        for (int c = 0; c < 32; ++c) {
            float4 v0 = __ldcs(p4 + (size_t)c * 60);
            float4 v1 = __ldcs(p4 + (size_t)c * 60 + 1);
            float hp = s_ph[g * 32 + c];
            float w  = s_sw[g * 32 + c];
            a0.x += tanh_fast(v0.x + hp) * w;
            a0.y += tanh_fast(v0.y + hp) * w;
            a0.z += tanh_fast(v0.z + hp) * w;
            a0.w += tanh_fast(v0.w + hp) * w;
            a1.x += tanh_fast(v1.x + hp) * w;
            a1.y += tanh_fast(v1.y + hp) * w;
            a1.z += tanh_fast(v1.z + hp) * w;
            a1.w += tanh_fast(v1.w + hp) * w;
        }
        *reinterpret_cast<float4*>(&s_part[g][8 * t])     = a0;
        *reinterpret_cast<float4*>(&s_part[g][8 * t + 4]) = a1;
    }
    __syncthreads();

    float eval = 0.f;
    if (tid < HWW) {
        #pragma unroll
        for (int gg = 0; gg < 16; ++gg) eval += s_part[gg][tid];
    }
    const int lane = tid & 31, wid = tid >> 5;

    float v = (tid < HWW) ? eval : -3.0e38f;
    #pragma unroll
    for (int o = 16; o; o >>= 1) v = fmaxf(v, __shfl_xor_sync(0xffffffffu, v, o));
    if (lane == 0) s_red[wid] = v;
    __syncthreads();
    float m = s_red[0];
    #pragma unroll
    for (int i = 1; i < 16; ++i) m = fmaxf(m, s_red[i]);

    float e = (tid < HWW) ? __expf(eval - m) : 0.f;
    float sv = e;
    #pragma unroll
    for (int o = 16; o; o >>= 1) sv += __shfl_xor_sync(0xffffffffu, sv, o);
    if (lane == 0) s_red2[wid] = sv;
    __syncthreads();
    float tot = 0.f;
    #pragma unroll
    for (int i = 0; i < 16; ++i) tot += s_red2[i];

    if (tid < HWW) {
        const float alpha = e / tot;
        g_alpha[(size_t)b * HWW + tid] = alpha;
        alphaT[(size_t)tid * BB + b] = alpha;
    }
    if (tid < EE) {
        g_xh[(size_t)b * KX + CC + tid] = __float2half_rn(emb[(size_t)b * EE + tid]);
    }
}

// ---------------------------------------------------------------------------
// Kernel 2: context GEMV. grid (8, B), 256 threads; warp per channel row.
// (R11-proven structure — paced loads, per-row reductions)
// ---------------------------------------------------------------------------
__global__ __launch_bounds__(256) void ctx_kernel(const float* __restrict__ cfo)
{
    const int b  = blockIdx.y;
    const int c0 = blockIdx.x * 64;
    const int tid = threadIdx.x;
    const int lane = tid & 31, w = tid >> 5;

    __shared__ __align__(16) float s_alpha[HWW];
    if (tid < HWW) s_alpha[tid] = g_alpha[(size_t)b * HWW + tid];
    __syncthreads();

    const float4* a4 = reinterpret_cast<const float4*>(s_alpha);
    float4 aa = a4[lane];
    float4 a2 = (lane < 28) ? a4[lane + 32] : make_float4(0.f, 0.f, 0.f, 0.f);

    #pragma unroll 2
    for (int r = 0; r < 8; ++r) {
        const int c = c0 + w * 8 + r;
        const float4* rp = reinterpret_cast<const float4*>(
            cfo + ((size_t)b * CC + c) * HWW);
        float4 vv = __ldcs(rp + lane);
        float s = vv.x * aa.x + vv.y * aa.y + vv.z * aa.z + vv.w * aa.w;
        if (lane < 28) {
            float4 v2 = __ldcs(rp + lane + 32);
            s += v2.x * a2.x + v2.y * a2.y + v2.z * a2.z + v2.w * a2.w;
        }
        #pragma unroll
        for (int o = 16; o; o >>= 1) s += __shfl_xor_sync(0xffffffffu, s, o);
        if (lane == 0) {
            g_xh[(size_t)b * KX + c] = __float2half_rn(s);
        }
    }
}

// ---------------------------------------------------------------------------
// Kernel 3: gate GEMMs, fp16 MMA, split-K=4, chunk K=32, 3-stage cp.async ring
// with ONE barrier per chunk (load(t+2) issued before compute(t)).
// Tile 64(M) x 64(N). grid (24, 8, 8): z&1 = gemm, z>>1 = split.
// ---------------------------------------------------------------------------
#define ASTR 40   // fp16 row stride: 80 bytes

__device__ __forceinline__ void mma16816(float* c, const uint32_t* a, const uint32_t* b) {
    asm volatile(
        "mma.sync.aligned.m16n8k16.row.col.f32.f16.f16.f32 "
        "{%0,%1,%2,%3}, {%4,%5,%6,%7}, {%8,%9}, {%0,%1,%2,%3};"
        : "+f"(c[0]), "+f"(c[1]), "+f"(c[2]), "+f"(c[3])
        : "r"(a[0]), "r"(a[1]), "r"(a[2]), "r"(a[3]),
          "r"(b[0]), "r"(b[1]));
}
__device__ __forceinline__ void ldsm4(uint32_t* r, const __half* p) {
    uint32_t a = (uint32_t)__cvta_generic_to_shared(p);
    asm volatile("ldmatrix.sync.aligned.m8n8.x4.shared.b16 {%0,%1,%2,%3}, [%4];"
                 : "=r"(r[0]), "=r"(r[1]), "=r"(r[2]), "=r"(r[3]) : "r"(a));
}
__device__ __forceinline__ void cpasync16(uint32_t dst, const void* src) {
    asm volatile("cp.async.cg.shared.global [%0], [%1], 16;" :: "r"(dst), "l"(src));
}

__global__ __launch_bounds__(128) void gemm_gates()
{
    const int z      = blockIdx.z;
    const int gemmi  = z & 1;       // 0: gi (K=640), 1: gh (K=512)
    const int split  = z >> 1;      // 0..3

    const __half* A = gemmi ? g_hh  : g_xh;
    const __half* B = gemmi ? g_whh : g_wih;
    float* outp = g_part[gemmi * 4 + split];
    const int K    = gemmi ? CC : KX;
    const int Kq   = K >> 2;        // 160 or 128
    const int koff = split * Kq;
    const int T    = Kq / 32;       // 5 or 4

    __shared__ __align__(16) __half sA[3][64 * ASTR];
    __shared__ __align__(16) __half sB[3][64 * ASTR];

    const int tid  = threadIdx.x;
    const int lane = tid & 31;
    const int wrp  = tid >> 5;
    const int warp_m = wrp >> 1;
    const int warp_n = wrp & 1;
    const int gID = lane >> 2;
    const int tig = lane & 3;
    const int m0 = blockIdx.y * 64;
    const int n0 = blockIdx.x * 64;

    const int a_rowl = lane & 15;
    const int a_kh   = (lane >> 4) * 8;
    const int b_rowl = ((lane >> 4) * 8) + (lane & 7);
    const int b_kh   = ((lane >> 3) & 1) * 8;

    const int lrow0 = tid >> 2,         lseg0 = (tid & 3) * 8;
    const int lrow1 = (tid + 128) >> 2, lseg1 = (tid & 3) * 8;

    float acc[2][4][4];
    #pragma unroll
    for (int i = 0; i < 2; ++i)
        #pragma unroll
        for (int j = 0; j < 4; ++j)
            #pragma unroll
            for (int k = 0; k < 4; ++k) acc[i][j][k] = 0.f;

    auto load_stage = [&](int s, int kt) {
        const size_t kbase = (size_t)koff + kt * 32;
        {
            size_t ga = (size_t)(m0 + lrow0) * K + kbase + lseg0;
            size_t gb = (size_t)(n0 + lrow0) * K + kbase + lseg0;
            int so = lrow0 * ASTR + lseg0;
            cpasync16((uint32_t)__cvta_generic_to_shared(&sA[s][so]), A + ga);
            cpasync16((uint32_t)__cvta_generic_to_shared(&sB[s][so]), B + gb);
        }
        {
            size_t ga = (size_t)(m0 + lrow1) * K + kbase + lseg1;
            size_t gb = (size_t)(n0 + lrow1) * K + kbase + lseg1;
            int so = lrow1 * ASTR + lseg1;
            cpasync16((uint32_t)__cvta_generic_to_shared(&sA[s][so]), A + ga);
            cpasync16((uint32_t)__cvta_generic_to_shared(&sB[s][so]), B + gb);
        }
        asm volatile("cp.async.commit_group;");
    };

    load_stage(0, 0);
    load_stage(1, 1);

    int st = 0;                      // stage of chunk t (mod 3)
    for (int t = 0; t < T; ++t) {
        if (t + 1 < T) { asm volatile("cp.async.wait_group 1;"); }
        else           { asm volatile("cp.async.wait_group 0;"); }
        __syncthreads();

        // issue load for chunk t+2 into the buffer last read at t-1
        if (t + 2 < T) {
            int s2 = st + 2; if (s2 >= 3) s2 -= 3;
            load_stage(s2, t + 2);
        }

        #pragma unroll
        for (int k8 = 0; k8 < 2; ++k8) {
            const int kb = k8 * 16;
            uint32_t ah[2][4];
            #pragma unroll
            for (int m2 = 0; m2 < 2; ++m2) {
                const int r = warp_m * 32 + m2 * 16 + a_rowl;
                ldsm4(ah[m2], &sA[st][r * ASTR + kb + a_kh]);
            }
            uint32_t bh[4][2];
            #pragma unroll
            for (int p = 0; p < 2; ++p) {
                const int r = warp_n * 32 + p * 16 + b_rowl;
                uint32_t t4[4];
                ldsm4(t4, &sB[st][r * ASTR + kb + b_kh]);
                bh[2 * p][0] = t4[0]; bh[2 * p][1] = t4[1];
                bh[2 * p + 1][0] = t4[2]; bh[2 * p + 1][1] = t4[3];
            }
            #pragma unroll
            for (int m2 = 0; m2 < 2; ++m2)
                #pragma unroll
                for (int n4 = 0; n4 < 4; ++n4)
                    mma16816(acc[m2][n4], ah[m2], bh[n4]);
        }
        if (++st == 3) st = 0;
    }

    #pragma unroll
    for (int m2 = 0; m2 < 2; ++m2) {
        #pragma unroll
        for (int n4 = 0; n4 < 4; ++n4) {
            int r = m0 + warp_m * 32 + m2 * 16 + gID;
            int cb = n0 + warp_n * 32 + n4 * 8 + tig * 2;
            float2 o0 = {acc[m2][n4][0], acc[m2][n4][1]};
            float2 o1 = {acc[m2][n4][2], acc[m2][n4][3]};
            *reinterpret_cast<float2*>(outp + (size_t)r * GATES + cb) = o0;
            *reinterpret_cast<float2*>(outp + (size_t)(r + 8) * GATES + cb) = o1;
        }
    }
}

// ---------------------------------------------------------------------------
// Kernel 4: GRU combine; sums 4 split-K partials per gemm plus biases.
// ---------------------------------------------------------------------------
__global__ __launch_bounds__(256) void gru_kernel(
    const float* __restrict__ h, const float* __restrict__ b_ih,
    const float* __restrict__ b_hh, float* __restrict__ out)
{
    const int i4 = blockIdx.x * 256 + threadIdx.x;
    const int b = i4 >> 7;
    const int c4 = i4 & 127;
    const size_t row = (size_t)b * GATES;

    float4 gi_r, gi_z, gi_n, gh_r, gh_z, gh_n;
    {
        const float4* bi = reinterpret_cast<const float4*>(b_ih) + c4;
        const float4* bh = reinterpret_cast<const float4*>(b_hh) + c4;
        gi_r = bi[0]; gi_z = bi[128]; gi_n = bi[256];
        gh_r = bh[0]; gh_z = bh[128]; gh_n = bh[256];
    }
    #pragma unroll
    for (int s = 0; s < 4; ++s) {
        const float4* pi = reinterpret_cast<const float4*>(g_part[s]     + row) + c4;
        const float4* pg = reinterpret_cast<const float4*>(g_part[4 + s] + row) + c4;
        float4 a = pi[0], bq = pi[128], cq = pi[256];
        float4 d = pg[0], e = pg[128],  f = pg[256];
        gi_r.x += a.x; gi_r.y += a.y; gi_r.z += a.z; gi_r.w += a.w;
        gi_z.x += bq.x; gi_z.y += bq.y; gi_z.z += bq.z; gi_z.w += bq.w;
        gi_n.x += cq.x; gi_n.y += cq.y; gi_n.z += cq.z; gi_n.w += cq.w;
        gh_r.x += d.x; gh_r.y += d.y; gh_r.z += d.z; gh_r.w += d.w;
        gh_z.x += e.x; gh_z.y += e.y; gh_z.z += e.z; gh_z.w += e.w;
        gh_n.x += f.x; gh_n.y += f.y; gh_n.z += f.z; gh_n.w += f.w;
    }

    float4 hv = reinterpret_cast<const float4*>(h)[i4];
    float4 o;
    {
        float r = sigmoid_fast(gi_r.x + gh_r.x), zz = sigmoid_fast(gi_z.x + gh_z.x);
        float n = tanh_fast(gi_n.x + r * gh_n.x);
        o.x = (1.f - zz) * n + zz * hv.x;
    }
    {
        float r = sigmoid_fast(gi_r.y + gh_r.y), zz = sigmoid_fast(gi_z.y + gh_z.y);
        float n = tanh_fast(gi_n.y + r * gh_n.y);
        o.y = (1.f - zz) * n + zz * hv.y;
    }
    {
        float r = sigmoid_fast(gi_r.z + gh_r.z), zz = sigmoid_fast(gi_z.z + gh_z.z);
        float n = tanh_fast(gi_n.z + r * gh_n.z);
        o.z = (1.f - zz) * n + zz * hv.z;
    }
    {
        float r = sigmoid_fast(gi_r.w + gh_r.w), zz = sigmoid_fast(gi_z.w + gh_z.w);
        float n = tanh_fast(gi_n.w + r * gh_n.w);
        o.w = (1.f - zz) * n + zz * hv.w;
    }
    reinterpret_cast<float4*>(out)[i4] = o;
}

// ---------------------------------------------------------------------------
extern "C" void kernel_launch(void* const* d_in, const int* in_sizes, int n_in,
                              void* d_out, int out_size) {
    const float* prev_hidden       = (const float*)d_in[0];
    const float* conv_feats        = (const float*)d_in[1];
    const float* conv_feats_origin = (const float*)d_in[2];
    const float* cur_embeddings    = (const float*)d_in[3];
    const float* score_w           = (const float*)d_in[4];
    const float* w_ih              = (const float*)d_in[5];
    const float* w_hh              = (const float*)d_in[6];
    const float* b_ih              = (const float*)d_in[7];
    const float* b_hh              = (const float*)d_in[8];

    float* out        = (float*)d_out;
    float* out_hidden = out;                      // [B, C]
    float* out_alphaT = out + (size_t)BB * CC;    // [HW, B]

    split3_kernel<<<(N1 + N2 + N3) / 1024, 256>>>(w_ih, w_hh, prev_hidden);

    score_kernel<<<BB, 512>>>(prev_hidden, conv_feats, cur_embeddings,
                              score_w, out_alphaT);

    dim3 gc(CC / 64, BB);                         // (8, 512)
    ctx_kernel<<<gc, 256>>>(conv_feats_origin);

    dim3 g(GATES / 64, BB / 64, 8);               // (24, 8, 8) = 1536 CTAs
    gemm_gates<<<g, 128>>>();

    gru_kernel<<<(BB * CC) / 1024, 256>>>(prev_hidden, b_ih, b_hh, out_hidden);
}

// round 14
// speedup vs baseline: 1.1195x; 1.0027x over previous
#include <cuda_runtime.h>
#include <cuda_fp16.h>
#include <cstdint>

#define BB   512
#define CC   512
#define EE   128
#define HWW  240
#define GATES 1536   // 3*C
#define KX    640    // C+E

// -------- scratch (static device arrays; no allocation allowed) -----------
// partials: index [gemm*4 + split][B*GATES]; gemm 0 = gi, 1 = gh
__device__ float g_part[8][BB * GATES];
__device__ float g_alpha[BB * HWW];

__device__ __half g_xh [BB * KX];     // fp16 x = [context, emb]
__device__ __half g_hh [BB * CC];     // fp16 prev_hidden
__device__ __half g_wih[GATES * KX];  // fp16 w_ih
__device__ __half g_whh[GATES * CC];  // fp16 w_hh

__device__ __forceinline__ float tanh_fast(float x) {
    float y; asm("tanh.approx.f32 %0, %1;" : "=f"(y) : "f"(x)); return y;
}
__device__ __forceinline__ float sigmoid_fast(float x) {
    return 0.5f * tanh_fast(0.5f * x) + 0.5f;
}

// ---------------------------------------------------------------------------
// split3: fp32 -> fp16 for w_ih, w_hh, prev_hidden; float4-wide.
// ---------------------------------------------------------------------------
#define N1 (GATES * KX)
#define N2 (GATES * CC)
#define N3 (BB * CC)

__global__ __launch_bounds__(256) void split3_kernel(
    const float* __restrict__ w_ih, const float* __restrict__ w_hh,
    const float* __restrict__ h)
{
    int i = blockIdx.x * 256 + threadIdx.x;
    const float* src; __half* dst; int off;
    if (i < N1 / 4)            { src = w_ih; dst = g_wih; off = i; }
    else if (i < (N1 + N2) / 4){ src = w_hh; dst = g_whh; off = i - N1 / 4; }
    else                       { src = h;    dst = g_hh;  off = i - (N1 + N2) / 4; }

    float4 v = reinterpret_cast<const float4*>(src)[off];
    __half2 p0 = __floats2half2_rn(v.x, v.y);
    __half2 p1 = __floats2half2_rn(v.z, v.w);
    uint2 u = {*(uint32_t*)&p0, *(uint32_t*)&p1};
    reinterpret_cast<uint2*>(dst)[off] = u;
}

// ---------------------------------------------------------------------------
// Kernel 1: score + softmax. One block per b, 512 threads.
// ---------------------------------------------------------------------------
__global__ __launch_bounds__(512) void score_kernel(
    const float* __restrict__ ph,
    const float* __restrict__ cf,
    const float* __restrict__ emb,
    const float* __restrict__ sw,
    float* __restrict__ alphaT)
{
    const int b   = blockIdx.x;
    const int tid = threadIdx.x;

    __shared__ __align__(16) float s_ph[CC];
    __shared__ __align__(16) float s_sw[CC];
    __shared__ __align__(16) float s_part[16][HWW];
    __shared__ float s_red[16];
    __shared__ float s_red2[16];

    for (int i = tid; i < CC; i += 512) {
        s_ph[i] = ph[(size_t)b * CC + i];
        s_sw[i] = sw[i];
    }
    __syncthreads();

    const int g = tid >> 5;
    const int t = tid & 31;
    if (t < 30) {
        const float4* p4 = reinterpret_cast<const float4*>(
            cf + ((size_t)b * CC + g * 32) * HWW) + 2 * t;
        float4 a0 = make_float4(0.f, 0.f, 0.f, 0.f);
        float4 a1 = make_float4(0.f, 0.f, 0.f, 0.f);
        #pragma unroll 4
        for (int c = 0; c < 32; ++c) {
            float4 v0 = __ldcs(p4 + (size_t)c * 60);
            float4 v1 = __ldcs(p4 + (size_t)c * 60 + 1);
            float hp = s_ph[g * 32 + c];
            float w  = s_sw[g * 32 + c];
            a0.x += tanh_fast(v0.x + hp) * w;
            a0.y += tanh_fast(v0.y + hp) * w;
            a0.z += tanh_fast(v0.z + hp) * w;
            a0.w += tanh_fast(v0.w + hp) * w;
            a1.x += tanh_fast(v1.x + hp) * w;
            a1.y += tanh_fast(v1.y + hp) * w;
            a1.z += tanh_fast(v1.z + hp) * w;
            a1.w += tanh_fast(v1.w + hp) * w;
        }
        *reinterpret_cast<float4*>(&s_part[g][8 * t])     = a0;
        *reinterpret_cast<float4*>(&s_part[g][8 * t + 4]) = a1;
    }
    __syncthreads();

    float eval = 0.f;
    if (tid < HWW) {
        #pragma unroll
        for (int gg = 0; gg < 16; ++gg) eval += s_part[gg][tid];
    }
    const int lane = tid & 31, wid = tid >> 5;

    float v = (tid < HWW) ? eval : -3.0e38f;
    #pragma unroll
    for (int o = 16; o; o >>= 1) v = fmaxf(v, __shfl_xor_sync(0xffffffffu, v, o));
    if (lane == 0) s_red[wid] = v;
    __syncthreads();
    float m = s_red[0];
    #pragma unroll
    for (int i = 1; i < 16; ++i) m = fmaxf(m, s_red[i]);

    float e = (tid < HWW) ? __expf(eval - m) : 0.f;
    float sv = e;
    #pragma unroll
    for (int o = 16; o; o >>= 1) sv += __shfl_xor_sync(0xffffffffu, sv, o);
    if (lane == 0) s_red2[wid] = sv;
    __syncthreads();
    float tot = 0.f;
    #pragma unroll
    for (int i = 0; i < 16; ++i) tot += s_red2[i];

    if (tid < HWW) {
        const float alpha = e / tot;
        g_alpha[(size_t)b * HWW + tid] = alpha;
        alphaT[(size_t)tid * BB + b] = alpha;
    }
    if (tid < EE) {
        g_xh[(size_t)b * KX + CC + tid] = __float2half_rn(emb[(size_t)b * EE + tid]);
    }
}

// ---------------------------------------------------------------------------
// Kernel 2: context GEMV. grid (8, B), 256 threads; warp per channel row.
// ---------------------------------------------------------------------------
__global__ __launch_bounds__(256) void ctx_kernel(const float* __restrict__ cfo)
{
    const int b  = blockIdx.y;
    const int c0 = blockIdx.x * 64;
    const int tid = threadIdx.x;
    const int lane = tid & 31, w = tid >> 5;

    __shared__ __align__(16) float s_alpha[HWW];
    if (tid < HWW) s_alpha[tid] = g_alpha[(size_t)b * HWW + tid];
    __syncthreads();

    const float4* a4 = reinterpret_cast<const float4*>(s_alpha);
    float4 aa = a4[lane];
    float4 a2 = (lane < 28) ? a4[lane + 32] : make_float4(0.f, 0.f, 0.f, 0.f);

    #pragma unroll 2
    for (int r = 0; r < 8; ++r) {
        const int c = c0 + w * 8 + r;
        const float4* rp = reinterpret_cast<const float4*>(
            cfo + ((size_t)b * CC + c) * HWW);
        float4 vv = __ldcs(rp + lane);
        float s = vv.x * aa.x + vv.y * aa.y + vv.z * aa.z + vv.w * aa.w;
        if (lane < 28) {
            float4 v2 = __ldcs(rp + lane + 32);
            s += v2.x * a2.x + v2.y * a2.y + v2.z * a2.z + v2.w * a2.w;
        }
        #pragma unroll
        for (int o = 16; o; o >>= 1) s += __shfl_xor_sync(0xffffffffu, s, o);
        if (lane == 0) {
            g_xh[(size_t)b * KX + c] = __float2half_rn(s);
        }
    }
}

// ---------------------------------------------------------------------------
// Kernel 3: gate GEMMs, fp16 MMA, split-K=4, chunk K=32, 4-stage cp.async ring
// with prefetch depth 3 (wait_group 2); one barrier per chunk.
// Tile 64(M) x 64(N). grid (24, 8, 8): z&1 = gemm, z>>1 = split.
// ---------------------------------------------------------------------------
#define ASTR 40   // fp16 row stride: 80 bytes

__device__ __forceinline__ void mma16816(float* c, const uint32_t* a, const uint32_t* b) {
    asm volatile(
        "mma.sync.aligned.m16n8k16.row.col.f32.f16.f16.f32 "
        "{%0,%1,%2,%3}, {%4,%5,%6,%7}, {%8,%9}, {%0,%1,%2,%3};"
        : "+f"(c[0]), "+f"(c[1]), "+f"(c[2]), "+f"(c[3])
        : "r"(a[0]), "r"(a[1]), "r"(a[2]), "r"(a[3]),
          "r"(b[0]), "r"(b[1]));
}
__device__ __forceinline__ void ldsm4(uint32_t* r, const __half* p) {
    uint32_t a = (uint32_t)__cvta_generic_to_shared(p);
    asm volatile("ldmatrix.sync.aligned.m8n8.x4.shared.b16 {%0,%1,%2,%3}, [%4];"
                 : "=r"(r[0]), "=r"(r[1]), "=r"(r[2]), "=r"(r[3]) : "r"(a));
}
__device__ __forceinline__ void cpasync16(uint32_t dst, const void* src) {
    asm volatile("cp.async.cg.shared.global [%0], [%1], 16;" :: "r"(dst), "l"(src));
}

__global__ __launch_bounds__(128) void gemm_gates()
{
    const int z      = blockIdx.z;
    const int gemmi  = z & 1;       // 0: gi (K=640), 1: gh (K=512)
    const int split  = z >> 1;      // 0..3

    const __half* A = gemmi ? g_hh  : g_xh;
    const __half* B = gemmi ? g_whh : g_wih;
    float* outp = g_part[gemmi * 4 + split];
    const int K    = gemmi ? CC : KX;
    const int Kq   = K >> 2;        // 160 or 128
    const int koff = split * Kq;
    const int T    = Kq / 32;       // 5 or 4

    __shared__ __align__(16) __half sA[4][64 * ASTR];
    __shared__ __align__(16) __half sB[4][64 * ASTR];

    const int tid  = threadIdx.x;
    const int lane = tid & 31;
    const int wrp  = tid >> 5;
    const int warp_m = wrp >> 1;
    const int warp_n = wrp & 1;
    const int gID = lane >> 2;
    const int tig = lane & 3;
    const int m0 = blockIdx.y * 64;
    const int n0 = blockIdx.x * 64;

    const int a_rowl = lane & 15;
    const int a_kh   = (lane >> 4) * 8;
    const int b_rowl = ((lane >> 4) * 8) + (lane & 7);
    const int b_kh   = ((lane >> 3) & 1) * 8;

    const int lrow0 = tid >> 2,         lseg0 = (tid & 3) * 8;
    const int lrow1 = (tid + 128) >> 2, lseg1 = (tid & 3) * 8;

    float acc[2][4][4];
    #pragma unroll
    for (int i = 0; i < 2; ++i)
        #pragma unroll
        for (int j = 0; j < 4; ++j)
            #pragma unroll
            for (int k = 0; k < 4; ++k) acc[i][j][k] = 0.f;

    auto load_stage = [&](int s, int kt) {
        const size_t kbase = (size_t)koff + kt * 32;
        {
            size_t ga = (size_t)(m0 + lrow0) * K + kbase + lseg0;
            size_t gb = (size_t)(n0 + lrow0) * K + kbase + lseg0;
            int so = lrow0 * ASTR + lseg0;
            cpasync16((uint32_t)__cvta_generic_to_shared(&sA[s][so]), A + ga);
            cpasync16((uint32_t)__cvta_generic_to_shared(&sB[s][so]), B + gb);
        }
        {
            size_t ga = (size_t)(m0 + lrow1) * K + kbase + lseg1;
            size_t gb = (size_t)(n0 + lrow1) * K + kbase + lseg1;
            int so = lrow1 * ASTR + lseg1;
            cpasync16((uint32_t)__cvta_generic_to_shared(&sA[s][so]), A + ga);
            cpasync16((uint32_t)__cvta_generic_to_shared(&sB[s][so]), B + gb);
        }
        asm volatile("cp.async.commit_group;");
    };

    // prologue: 3 stages in flight
    load_stage(0, 0);
    load_stage(1, 1);
    if (T > 2) load_stage(2, 2);

    int st = 0;                      // stage of chunk t (mod 4)
    for (int t = 0; t < T; ++t) {
        // groups outstanding at this point: t .. min(T-1, t+2)
        if (t + 3 <= T)      { asm volatile("cp.async.wait_group 2;"); }
        else if (t + 2 <= T) { asm volatile("cp.async.wait_group 1;"); }
        else                 { asm volatile("cp.async.wait_group 0;"); }
        __syncthreads();

        // issue load for chunk t+3 into the buffer last read at t-1
        if (t + 3 < T) {
            int s3 = st + 3; if (s3 >= 4) s3 -= 4;
            load_stage(s3, t + 3);
        }

        #pragma unroll
        for (int k8 = 0; k8 < 2; ++k8) {
            const int kb = k8 * 16;
            uint32_t ah[2][4];
            #pragma unroll
            for (int m2 = 0; m2 < 2; ++m2) {
                const int r = warp_m * 32 + m2 * 16 + a_rowl;
                ldsm4(ah[m2], &sA[st][r * ASTR + kb + a_kh]);
            }
            uint32_t bh[4][2];
            #pragma unroll
            for (int p = 0; p < 2; ++p) {
                const int r = warp_n * 32 + p * 16 + b_rowl;
                uint32_t t4[4];
                ldsm4(t4, &sB[st][r * ASTR + kb + b_kh]);
                bh[2 * p][0] = t4[0]; bh[2 * p][1] = t4[1];
                bh[2 * p + 1][0] = t4[2]; bh[2 * p + 1][1] = t4[3];
            }
            #pragma unroll
            for (int m2 = 0; m2 < 2; ++m2)
                #pragma unroll
                for (int n4 = 0; n4 < 4; ++n4)
                    mma16816(acc[m2][n4], ah[m2], bh[n4]);
        }
        if (++st == 4) st = 0;
    }

    #pragma unroll
    for (int m2 = 0; m2 < 2; ++m2) {
        #pragma unroll
        for (int n4 = 0; n4 < 4; ++n4) {
            int r = m0 + warp_m * 32 + m2 * 16 + gID;
            int cb = n0 + warp_n * 32 + n4 * 8 + tig * 2;
            float2 o0 = {acc[m2][n4][0], acc[m2][n4][1]};
            float2 o1 = {acc[m2][n4][2], acc[m2][n4][3]};
            *reinterpret_cast<float2*>(outp + (size_t)r * GATES + cb) = o0;
            *reinterpret_cast<float2*>(outp + (size_t)(r + 8) * GATES + cb) = o1;
        }
    }
}

// ---------------------------------------------------------------------------
// Kernel 4: GRU combine; sums 4 split-K partials per gemm plus biases.
// ---------------------------------------------------------------------------
__global__ __launch_bounds__(256) void gru_kernel(
    const float* __restrict__ h, const float* __restrict__ b_ih,
    const float* __restrict__ b_hh, float* __restrict__ out)
{
    const int i4 = blockIdx.x * 256 + threadIdx.x;
    const int b = i4 >> 7;
    const int c4 = i4 & 127;
    const size_t row = (size_t)b * GATES;

    float4 gi_r, gi_z, gi_n, gh_r, gh_z, gh_n;
    {
        const float4* bi = reinterpret_cast<const float4*>(b_ih) + c4;
        const float4* bh = reinterpret_cast<const float4*>(b_hh) + c4;
        gi_r = bi[0]; gi_z = bi[128]; gi_n = bi[256];
        gh_r = bh[0]; gh_z = bh[128]; gh_n = bh[256];
    }
    #pragma unroll
    for (int s = 0; s < 4; ++s) {
        const float4* pi = reinterpret_cast<const float4*>(g_part[s]     + row) + c4;
        const float4* pg = reinterpret_cast<const float4*>(g_part[4 + s] + row) + c4;
        float4 a = pi[0], bq = pi[128], cq = pi[256];
        float4 d = pg[0], e = pg[128],  f = pg[256];
        gi_r.x += a.x; gi_r.y += a.y; gi_r.z += a.z; gi_r.w += a.w;
        gi_z.x += bq.x; gi_z.y += bq.y; gi_z.z += bq.z; gi_z.w += bq.w;
        gi_n.x += cq.x; gi_n.y += cq.y; gi_n.z += cq.z; gi_n.w += cq.w;
        gh_r.x += d.x; gh_r.y += d.y; gh_r.z += d.z; gh_r.w += d.w;
        gh_z.x += e.x; gh_z.y += e.y; gh_z.z += e.z; gh_z.w += e.w;
        gh_n.x += f.x; gh_n.y += f.y; gh_n.z += f.z; gh_n.w += f.w;
    }

    float4 hv = reinterpret_cast<const float4*>(h)[i4];
    float4 o;
    {
        float r = sigmoid_fast(gi_r.x + gh_r.x), zz = sigmoid_fast(gi_z.x + gh_z.x);
        float n = tanh_fast(gi_n.x + r * gh_n.x);
        o.x = (1.f - zz) * n + zz * hv.x;
    }
    {
        float r = sigmoid_fast(gi_r.y + gh_r.y), zz = sigmoid_fast(gi_z.y + gh_z.y);
        float n = tanh_fast(gi_n.y + r * gh_n.y);
        o.y = (1.f - zz) * n + zz * hv.y;
    }
    {
        float r = sigmoid_fast(gi_r.z + gh_r.z), zz = sigmoid_fast(gi_z.z + gh_z.z);
        float n = tanh_fast(gi_n.z + r * gh_n.z);
        o.z = (1.f - zz) * n + zz * hv.z;
    }
    {
        float r = sigmoid_fast(gi_r.w + gh_r.w), zz = sigmoid_fast(gi_z.w + gh_z.w);
        float n = tanh_fast(gi_n.w + r * gh_n.w);
        o.w = (1.f - zz) * n + zz * hv.w;
    }
    reinterpret_cast<float4*>(out)[i4] = o;
}

// ---------------------------------------------------------------------------
extern "C" void kernel_launch(void* const* d_in, const int* in_sizes, int n_in,
                              void* d_out, int out_size) {
    const float* prev_hidden       = (const float*)d_in[0];
    const float* conv_feats        = (const float*)d_in[1];
    const float* conv_feats_origin = (const float*)d_in[2];
    const float* cur_embeddings    = (const float*)d_in[3];
    const float* score_w           = (const float*)d_in[4];
    const float* w_ih              = (const float*)d_in[5];
    const float* w_hh              = (const float*)d_in[6];
    const float* b_ih              = (const float*)d_in[7];
    const float* b_hh              = (const float*)d_in[8];

    float* out        = (float*)d_out;
    float* out_hidden = out;                      // [B, C]
    float* out_alphaT = out + (size_t)BB * CC;    // [HW, B]

    split3_kernel<<<(N1 + N2 + N3) / 1024, 256>>>(w_ih, w_hh, prev_hidden);

    score_kernel<<<BB, 512>>>(prev_hidden, conv_feats, cur_embeddings,
                              score_w, out_alphaT);

    dim3 gc(CC / 64, BB);                         // (8, 512)
    ctx_kernel<<<gc, 256>>>(conv_feats_origin);

    dim3 g(GATES / 64, BB / 64, 8);               // (24, 8, 8) = 1536 CTAs
    gemm_gates<<<g, 128>>>();

    gru_kernel<<<(BB * CC) / 1024, 256>>>(prev_hidden, b_ih, b_hh, out_hidden);
}

// round 15
// speedup vs baseline: 1.1422x; 1.0202x over previous
#include <cuda_runtime.h>
#include <cuda_fp16.h>
#include <cstdint>

#define BB   512
#define CC   512
#define EE   128
#define HWW  240
#define GATES 1536   // 3*C
#define KX    640    // C+E

// -------- scratch (static device arrays; no allocation allowed) -----------
// partials: index [gemm*4 + split][B*GATES]; gemm 0 = gi, 1 = gh
__device__ float g_part[8][BB * GATES];
__device__ float g_alpha[BB * HWW];

__device__ __half g_xh [BB * KX];     // fp16 x = [context, emb]
__device__ __half g_hh [BB * CC];     // fp16 prev_hidden
__device__ __half g_wih[GATES * KX];  // fp16 w_ih
__device__ __half g_whh[GATES * CC];  // fp16 w_hh

__device__ __forceinline__ float tanh_fast(float x) {
    float y; asm("tanh.approx.f32 %0, %1;" : "=f"(y) : "f"(x)); return y;
}
__device__ __forceinline__ float sigmoid_fast(float x) {
    return 0.5f * tanh_fast(0.5f * x) + 0.5f;
}

// ---------------------------------------------------------------------------
// split3: fp32 -> fp16 for w_ih, w_hh, prev_hidden; float4-wide.
// ---------------------------------------------------------------------------
#define N1 (GATES * KX)
#define N2 (GATES * CC)
#define N3 (BB * CC)

__global__ __launch_bounds__(256) void split3_kernel(
    const float* __restrict__ w_ih, const float* __restrict__ w_hh,
    const float* __restrict__ h)
{
    int i = blockIdx.x * 256 + threadIdx.x;
    const float* src; __half* dst; int off;
    if (i < N1 / 4)            { src = w_ih; dst = g_wih; off = i; }
    else if (i < (N1 + N2) / 4){ src = w_hh; dst = g_whh; off = i - N1 / 4; }
    else                       { src = h;    dst = g_hh;  off = i - (N1 + N2) / 4; }

    float4 v = reinterpret_cast<const float4*>(src)[off];
    __half2 p0 = __floats2half2_rn(v.x, v.y);
    __half2 p1 = __floats2half2_rn(v.z, v.w);
    uint2 u = {*(uint32_t*)&p0, *(uint32_t*)&p1};
    reinterpret_cast<uint2*>(dst)[off] = u;
}

// ---------------------------------------------------------------------------
// Kernel 1: score + softmax. One block per b, 512 threads.
// ---------------------------------------------------------------------------
__global__ __launch_bounds__(512) void score_kernel(
    const float* __restrict__ ph,
    const float* __restrict__ cf,
    const float* __restrict__ emb,
    const float* __restrict__ sw,
    float* __restrict__ alphaT)
{
    const int b   = blockIdx.x;
    const int tid = threadIdx.x;

    __shared__ __align__(16) float s_ph[CC];
    __shared__ __align__(16) float s_sw[CC];
    __shared__ __align__(16) float s_part[16][HWW];
    __shared__ float s_red[16];
    __shared__ float s_red2[16];

    for (int i = tid; i < CC; i += 512) {
        s_ph[i] = ph[(size_t)b * CC + i];
        s_sw[i] = sw[i];
    }
    __syncthreads();

    const int g = tid >> 5;
    const int t = tid & 31;
    if (t < 30) {
        const float4* p4 = reinterpret_cast<const float4*>(
            cf + ((size_t)b * CC + g * 32) * HWW) + 2 * t;
        float4 a0 = make_float4(0.f, 0.f, 0.f, 0.f);
        float4 a1 = make_float4(0.f, 0.f, 0.f, 0.f);
        #pragma unroll 4
        for (int c = 0; c < 32; ++c) {
            float4 v0 = __ldcs(p4 + (size_t)c * 60);
            float4 v1 = __ldcs(p4 + (size_t)c * 60 + 1);
            float hp = s_ph[g * 32 + c];
            float w  = s_sw[g * 32 + c];
            a0.x += tanh_fast(v0.x + hp) * w;
            a0.y += tanh_fast(v0.y + hp) * w;
            a0.z += tanh_fast(v0.z + hp) * w;
            a0.w += tanh_fast(v0.w + hp) * w;
            a1.x += tanh_fast(v1.x + hp) * w;
            a1.y += tanh_fast(v1.y + hp) * w;
            a1.z += tanh_fast(v1.z + hp) * w;
            a1.w += tanh_fast(v1.w + hp) * w;
        }
        *reinterpret_cast<float4*>(&s_part[g][8 * t])     = a0;
        *reinterpret_cast<float4*>(&s_part[g][8 * t + 4]) = a1;
    }
    __syncthreads();

    float eval = 0.f;
    if (tid < HWW) {
        #pragma unroll
        for (int gg = 0; gg < 16; ++gg) eval += s_part[gg][tid];
    }
    const int lane = tid & 31, wid = tid >> 5;

    float v = (tid < HWW) ? eval : -3.0e38f;
    #pragma unroll
    for (int o = 16; o; o >>= 1) v = fmaxf(v, __shfl_xor_sync(0xffffffffu, v, o));
    if (lane == 0) s_red[wid] = v;
    __syncthreads();
    float m = s_red[0];
    #pragma unroll
    for (int i = 1; i < 16; ++i) m = fmaxf(m, s_red[i]);

    float e = (tid < HWW) ? __expf(eval - m) : 0.f;
    float sv = e;
    #pragma unroll
    for (int o = 16; o; o >>= 1) sv += __shfl_xor_sync(0xffffffffu, sv, o);
    if (lane == 0) s_red2[wid] = sv;
    __syncthreads();
    float tot = 0.f;
    #pragma unroll
    for (int i = 0; i < 16; ++i) tot += s_red2[i];

    if (tid < HWW) {
        const float alpha = e / tot;
        g_alpha[(size_t)b * HWW + tid] = alpha;
        alphaT[(size_t)tid * BB + b] = alpha;
    }
    if (tid < EE) {
        g_xh[(size_t)b * KX + CC + tid] = __float2half_rn(emb[(size_t)b * EE + tid]);
    }
}

// ---------------------------------------------------------------------------
// Kernel 2: context GEMV. grid (8, B), 256 threads; warp per channel row.
// ---------------------------------------------------------------------------
__global__ __launch_bounds__(256) void ctx_kernel(const float* __restrict__ cfo)
{
    const int b  = blockIdx.y;
    const int c0 = blockIdx.x * 64;
    const int tid = threadIdx.x;
    const int lane = tid & 31, w = tid >> 5;

    __shared__ __align__(16) float s_alpha[HWW];
    if (tid < HWW) s_alpha[tid] = g_alpha[(size_t)b * HWW + tid];
    __syncthreads();

    const float4* a4 = reinterpret_cast<const float4*>(s_alpha);
    float4 aa = a4[lane];
    float4 a2 = (lane < 28) ? a4[lane + 32] : make_float4(0.f, 0.f, 0.f, 0.f);

    #pragma unroll 2
    for (int r = 0; r < 8; ++r) {
        const int c = c0 + w * 8 + r;
        const float4* rp = reinterpret_cast<const float4*>(
            cfo + ((size_t)b * CC + c) * HWW);
        float4 vv = __ldcs(rp + lane);
        float s = vv.x * aa.x + vv.y * aa.y + vv.z * aa.z + vv.w * aa.w;
        if (lane < 28) {
            float4 v2 = __ldcs(rp + lane + 32);
            s += v2.x * a2.x + v2.y * a2.y + v2.z * a2.z + v2.w * a2.w;
        }
        #pragma unroll
        for (int o = 16; o; o >>= 1) s += __shfl_xor_sync(0xffffffffu, s, o);
        if (lane == 0) {
            g_xh[(size_t)b * KX + c] = __float2half_rn(s);
        }
    }
}

// ---------------------------------------------------------------------------
// Kernel 3: gate GEMMs, fp16 MMA, split-K=4, chunk K=32, 3-stage cp.async ring
// (one barrier per chunk). PDL: gh CTAs skip griddepsync (no ctx dependency);
// gi CTAs sync before reading g_xh.
// Tile 64(M) x 64(N). grid (24, 8, 8): z&1 = gemm, z>>1 = split.
// ---------------------------------------------------------------------------
#define ASTR 40   // fp16 row stride: 80 bytes

__device__ __forceinline__ void mma16816(float* c, const uint32_t* a, const uint32_t* b) {
    asm volatile(
        "mma.sync.aligned.m16n8k16.row.col.f32.f16.f16.f32 "
        "{%0,%1,%2,%3}, {%4,%5,%6,%7}, {%8,%9}, {%0,%1,%2,%3};"
        : "+f"(c[0]), "+f"(c[1]), "+f"(c[2]), "+f"(c[3])
        : "r"(a[0]), "r"(a[1]), "r"(a[2]), "r"(a[3]),
          "r"(b[0]), "r"(b[1]));
}
__device__ __forceinline__ void ldsm4(uint32_t* r, const __half* p) {
    uint32_t a = (uint32_t)__cvta_generic_to_shared(p);
    asm volatile("ldmatrix.sync.aligned.m8n8.x4.shared.b16 {%0,%1,%2,%3}, [%4];"
                 : "=r"(r[0]), "=r"(r[1]), "=r"(r[2]), "=r"(r[3]) : "r"(a));
}
__device__ __forceinline__ void cpasync16(uint32_t dst, const void* src) {
    asm volatile("cp.async.cg.shared.global [%0], [%1], 16;" :: "r"(dst), "l"(src));
}

__global__ __launch_bounds__(128) void gemm_gates()
{
    const int z      = blockIdx.z;
    const int gemmi  = z & 1;       // 0: gi (K=640), 1: gh (K=512)
    const int split  = z >> 1;      // 0..3

    // gi reads g_xh (written by ctx) -> must wait for the preceding grid.
    // gh reads only h/w splits (written 2 kernels earlier) -> free to run early.
    if (gemmi == 0) cudaGridDependencySynchronize();

    const __half* A = gemmi ? g_hh  : g_xh;
    const __half* B = gemmi ? g_whh : g_wih;
    float* outp = g_part[gemmi * 4 + split];
    const int K    = gemmi ? CC : KX;
    const int Kq   = K >> 2;        // 160 or 128
    const int koff = split * Kq;
    const int T    = Kq / 32;       // 5 or 4

    __shared__ __align__(16) __half sA[3][64 * ASTR];
    __shared__ __align__(16) __half sB[3][64 * ASTR];

    const int tid  = threadIdx.x;
    const int lane = tid & 31;
    const int wrp  = tid >> 5;
    const int warp_m = wrp >> 1;
    const int warp_n = wrp & 1;
    const int gID = lane >> 2;
    const int tig = lane & 3;
    const int m0 = blockIdx.y * 64;
    const int n0 = blockIdx.x * 64;

    const int a_rowl = lane & 15;
    const int a_kh   = (lane >> 4) * 8;
    const int b_rowl = ((lane >> 4) * 8) + (lane & 7);
    const int b_kh   = ((lane >> 3) & 1) * 8;

    const int lrow0 = tid >> 2,         lseg0 = (tid & 3) * 8;
    const int lrow1 = (tid + 128) >> 2, lseg1 = (tid & 3) * 8;

    float acc[2][4][4];
    #pragma unroll
    for (int i = 0; i < 2; ++i)
        #pragma unroll
        for (int j = 0; j < 4; ++j)
            #pragma unroll
            for (int k = 0; k < 4; ++k) acc[i][j][k] = 0.f;

    auto load_stage = [&](int s, int kt) {
        const size_t kbase = (size_t)koff + kt * 32;
        {
            size_t ga = (size_t)(m0 + lrow0) * K + kbase + lseg0;
            size_t gb = (size_t)(n0 + lrow0) * K + kbase + lseg0;
            int so = lrow0 * ASTR + lseg0;
            cpasync16((uint32_t)__cvta_generic_to_shared(&sA[s][so]), A + ga);
            cpasync16((uint32_t)__cvta_generic_to_shared(&sB[s][so]), B + gb);
        }
        {
            size_t ga = (size_t)(m0 + lrow1) * K + kbase + lseg1;
            size_t gb = (size_t)(n0 + lrow1) * K + kbase + lseg1;
            int so = lrow1 * ASTR + lseg1;
            cpasync16((uint32_t)__cvta_generic_to_shared(&sA[s][so]), A + ga);
            cpasync16((uint32_t)__cvta_generic_to_shared(&sB[s][so]), B + gb);
        }
        asm volatile("cp.async.commit_group;");
    };

    load_stage(0, 0);
    load_stage(1, 1);

    int st = 0;                      // stage of chunk t (mod 3)
    for (int t = 0; t < T; ++t) {
        if (t + 1 < T) { asm volatile("cp.async.wait_group 1;"); }
        else           { asm volatile("cp.async.wait_group 0;"); }
        __syncthreads();

        // issue load for chunk t+2 into the buffer last read at t-1
        if (t + 2 < T) {
            int s2 = st + 2; if (s2 >= 3) s2 -= 3;
            load_stage(s2, t + 2);
        }

        #pragma unroll
        for (int k8 = 0; k8 < 2; ++k8) {
            const int kb = k8 * 16;
            uint32_t ah[2][4];
            #pragma unroll
            for (int m2 = 0; m2 < 2; ++m2) {
                const int r = warp_m * 32 + m2 * 16 + a_rowl;
                ldsm4(ah[m2], &sA[st][r * ASTR + kb + a_kh]);
            }
            uint32_t bh[4][2];
            #pragma unroll
            for (int p = 0; p < 2; ++p) {
                const int r = warp_n * 32 + p * 16 + b_rowl;
                uint32_t t4[4];
                ldsm4(t4, &sB[st][r * ASTR + kb + b_kh]);
                bh[2 * p][0] = t4[0]; bh[2 * p][1] = t4[1];
                bh[2 * p + 1][0] = t4[2]; bh[2 * p + 1][1] = t4[3];
            }
            #pragma unroll
            for (int m2 = 0; m2 < 2; ++m2)
                #pragma unroll
                for (int n4 = 0; n4 < 4; ++n4)
                    mma16816(acc[m2][n4], ah[m2], bh[n4]);
        }
        if (++st == 3) st = 0;
    }

    #pragma unroll
    for (int m2 = 0; m2 < 2; ++m2) {
        #pragma unroll
        for (int n4 = 0; n4 < 4; ++n4) {
            int r = m0 + warp_m * 32 + m2 * 16 + gID;
            int cb = n0 + warp_n * 32 + n4 * 8 + tig * 2;
            float2 o0 = {acc[m2][n4][0], acc[m2][n4][1]};
            float2 o1 = {acc[m2][n4][2], acc[m2][n4][3]};
            *reinterpret_cast<float2*>(outp + (size_t)r * GATES + cb) = o0;
            *reinterpret_cast<float2*>(outp + (size_t)(r + 8) * GATES + cb) = o1;
        }
    }
}

// ---------------------------------------------------------------------------
// Kernel 4: GRU combine; sums 4 split-K partials per gemm plus biases.
// PDL consumer: waits for gemm grid before reading partials.
// ---------------------------------------------------------------------------
__global__ __launch_bounds__(256) void gru_kernel(
    const float* __restrict__ h, const float* __restrict__ b_ih,
    const float* __restrict__ b_hh, float* __restrict__ out)
{
    cudaGridDependencySynchronize();

    const int i4 = blockIdx.x * 256 + threadIdx.x;
    const int b = i4 >> 7;
    const int c4 = i4 & 127;
    const size_t row = (size_t)b * GATES;

    float4 gi_r, gi_z, gi_n, gh_r, gh_z, gh_n;
    {
        const float4* bi = reinterpret_cast<const float4*>(b_ih) + c4;
        const float4* bh = reinterpret_cast<const float4*>(b_hh) + c4;
        gi_r = bi[0]; gi_z = bi[128]; gi_n = bi[256];
        gh_r = bh[0]; gh_z = bh[128]; gh_n = bh[256];
    }
    #pragma unroll
    for (int s = 0; s < 4; ++s) {
        const float4* pi = reinterpret_cast<const float4*>(g_part[s]     + row) + c4;
        const float4* pg = reinterpret_cast<const float4*>(g_part[4 + s] + row) + c4;
        float4 a = pi[0], bq = pi[128], cq = pi[256];
        float4 d = pg[0], e = pg[128],  f = pg[256];
        gi_r.x += a.x; gi_r.y += a.y; gi_r.z += a.z; gi_r.w += a.w;
        gi_z.x += bq.x; gi_z.y += bq.y; gi_z.z += bq.z; gi_z.w += bq.w;
        gi_n.x += cq.x; gi_n.y += cq.y; gi_n.z += cq.z; gi_n.w += cq.w;
        gh_r.x += d.x; gh_r.y += d.y; gh_r.z += d.z; gh_r.w += d.w;
        gh_z.x += e.x; gh_z.y += e.y; gh_z.z += e.z; gh_z.w += e.w;
        gh_n.x += f.x; gh_n.y += f.y; gh_n.z += f.z; gh_n.w += f.w;
    }

    float4 hv = reinterpret_cast<const float4*>(h)[i4];
    float4 o;
    {
        float r = sigmoid_fast(gi_r.x + gh_r.x), zz = sigmoid_fast(gi_z.x + gh_z.x);
        float n = tanh_fast(gi_n.x + r * gh_n.x);
        o.x = (1.f - zz) * n + zz * hv.x;
    }
    {
        float r = sigmoid_fast(gi_r.y + gh_r.y), zz = sigmoid_fast(gi_z.y + gh_z.y);
        float n = tanh_fast(gi_n.y + r * gh_n.y);
        o.y = (1.f - zz) * n + zz * hv.y;
    }
    {
        float r = sigmoid_fast(gi_r.z + gh_r.z), zz = sigmoid_fast(gi_z.z + gh_z.z);
        float n = tanh_fast(gi_n.z + r * gh_n.z);
        o.z = (1.f - zz) * n + zz * hv.z;
    }
    {
        float r = sigmoid_fast(gi_r.w + gh_r.w), zz = sigmoid_fast(gi_z.w + gh_z.w);
        float n = tanh_fast(gi_n.w + r * gh_n.w);
        o.w = (1.f - zz) * n + zz * hv.w;
    }
    reinterpret_cast<float4*>(out)[i4] = o;
}

// ---------------------------------------------------------------------------
extern "C" void kernel_launch(void* const* d_in, const int* in_sizes, int n_in,
                              void* d_out, int out_size) {
    const float* prev_hidden       = (const float*)d_in[0];
    const float* conv_feats        = (const float*)d_in[1];
    const float* conv_feats_origin = (const float*)d_in[2];
    const float* cur_embeddings    = (const float*)d_in[3];
    const float* score_w           = (const float*)d_in[4];
    const float* w_ih              = (const float*)d_in[5];
    const float* w_hh              = (const float*)d_in[6];
    const float* b_ih              = (const float*)d_in[7];
    const float* b_hh              = (const float*)d_in[8];

    float* out        = (float*)d_out;
    float* out_hidden = out;                      // [B, C]
    float* out_alphaT = out + (size_t)BB * CC;    // [HW, B]

    split3_kernel<<<(N1 + N2 + N3) / 1024, 256>>>(w_ih, w_hh, prev_hidden);

    score_kernel<<<BB, 512>>>(prev_hidden, conv_feats, cur_embeddings,
                              score_w, out_alphaT);

    dim3 gc(CC / 64, BB);                         // (8, 512)
    ctx_kernel<<<gc, 256>>>(conv_feats_origin);

    // gemm with PDL: launches while ctx drains; gh CTAs run immediately,
    // gi CTAs griddepsync on ctx completion.
    {
        cudaLaunchConfig_t cfg = {};
        cfg.gridDim  = dim3(GATES / 64, BB / 64, 8);   // (24, 8, 8)
        cfg.blockDim = dim3(128, 1, 1);
        cudaLaunchAttribute attr[1];
        attr[0].id = cudaLaunchAttributeProgrammaticStreamSerialization;
        attr[0].val.programmaticStreamSerializationAllowed = 1;
        cfg.attrs = attr;
        cfg.numAttrs = 1;
        cudaLaunchKernelEx(&cfg, gemm_gates);
    }

    // gru with PDL: prologue overlaps gemm drain; griddepsync before reads.
    {
        cudaLaunchConfig_t cfg = {};
        cfg.gridDim  = dim3((BB * CC) / 1024, 1, 1);
        cfg.blockDim = dim3(256, 1, 1);
        cudaLaunchAttribute attr[1];
        attr[0].id = cudaLaunchAttributeProgrammaticStreamSerialization;
        attr[0].val.programmaticStreamSerializationAllowed = 1;
        cfg.attrs = attr;
        cfg.numAttrs = 1;
        cudaLaunchKernelEx(&cfg, gru_kernel, prev_hidden, b_ih, b_hh, out_hidden);
    }
}

// round 16
// speedup vs baseline: 1.1440x; 1.0016x over previous
#include <cuda_runtime.h>
#include <cuda_fp16.h>
#include <cstdint>

#define BB   512
#define CC   512
#define EE   128
#define HWW  240
#define GATES 1536   // 3*C
#define KX    640    // C+E

// -------- scratch (static device arrays; no allocation allowed) -----------
// partials: index [gemm*4 + split][B*GATES]; gemm 0 = gi, 1 = gh
__device__ float g_part[8][BB * GATES];
__device__ float g_alpha[BB * HWW];

__device__ __half g_xh [BB * KX];     // fp16 x = [context, emb]
__device__ __half g_hh [BB * CC];     // fp16 prev_hidden
__device__ __half g_wih[GATES * KX];  // fp16 w_ih
__device__ __half g_whh[GATES * CC];  // fp16 w_hh

__device__ __forceinline__ float tanh_fast(float x) {
    float y; asm("tanh.approx.f32 %0, %1;" : "=f"(y) : "f"(x)); return y;
}
__device__ __forceinline__ float sigmoid_fast(float x) {
    return 0.5f * tanh_fast(0.5f * x) + 0.5f;
}

// ---------------------------------------------------------------------------
// split3: fp32 -> fp16 for w_ih, w_hh, prev_hidden; float4-wide.
// Triggers PDL immediately: score (no data dependence) launches concurrently.
// ---------------------------------------------------------------------------
#define N1 (GATES * KX)
#define N2 (GATES * CC)
#define N3 (BB * CC)

__global__ __launch_bounds__(256) void split3_kernel(
    const float* __restrict__ w_ih, const float* __restrict__ w_hh,
    const float* __restrict__ h)
{
    cudaTriggerProgrammaticLaunchCompletion();

    int i = blockIdx.x * 256 + threadIdx.x;
    const float* src; __half* dst; int off;
    if (i < N1 / 4)            { src = w_ih; dst = g_wih; off = i; }
    else if (i < (N1 + N2) / 4){ src = w_hh; dst = g_whh; off = i - N1 / 4; }
    else                       { src = h;    dst = g_hh;  off = i - (N1 + N2) / 4; }

    float4 v = reinterpret_cast<const float4*>(src)[off];
    __half2 p0 = __floats2half2_rn(v.x, v.y);
    __half2 p1 = __floats2half2_rn(v.z, v.w);
    uint2 u = {*(uint32_t*)&p0, *(uint32_t*)&p1};
    reinterpret_cast<uint2*>(dst)[off] = u;
}

// ---------------------------------------------------------------------------
// Kernel 1: score + softmax. One block per b, 512 threads.
// PDL-launched, NO griddepsync: reads only pure inputs; writes disjoint from
// split3's writes -> safe to run fully concurrent with split3.
// ---------------------------------------------------------------------------
__global__ __launch_bounds__(512) void score_kernel(
    const float* __restrict__ ph,
    const float* __restrict__ cf,
    const float* __restrict__ emb,
    const float* __restrict__ sw,
    float* __restrict__ alphaT)
{
    const int b   = blockIdx.x;
    const int tid = threadIdx.x;

    __shared__ __align__(16) float s_ph[CC];
    __shared__ __align__(16) float s_sw[CC];
    __shared__ __align__(16) float s_part[16][HWW];
    __shared__ float s_red[16];
    __shared__ float s_red2[16];

    for (int i = tid; i < CC; i += 512) {
        s_ph[i] = ph[(size_t)b * CC + i];
        s_sw[i] = sw[i];
    }
    __syncthreads();

    const int g = tid >> 5;
    const int t = tid & 31;
    if (t < 30) {
        const float4* p4 = reinterpret_cast<const float4*>(
            cf + ((size_t)b * CC + g * 32) * HWW) + 2 * t;
        float4 a0 = make_float4(0.f, 0.f, 0.f, 0.f);
        float4 a1 = make_float4(0.f, 0.f, 0.f, 0.f);
        #pragma unroll 4
        for (int c = 0; c < 32; ++c) {
            float4 v0 = __ldcs(p4 + (size_t)c * 60);
            float4 v1 = __ldcs(p4 + (size_t)c * 60 + 1);
            float hp = s_ph[g * 32 + c];
            float w  = s_sw[g * 32 + c];
            a0.x += tanh_fast(v0.x + hp) * w;
            a0.y += tanh_fast(v0.y + hp) * w;
            a0.z += tanh_fast(v0.z + hp) * w;
            a0.w += tanh_fast(v0.w + hp) * w;
            a1.x += tanh_fast(v1.x + hp) * w;
            a1.y += tanh_fast(v1.y + hp) * w;
            a1.z += tanh_fast(v1.z + hp) * w;
            a1.w += tanh_fast(v1.w + hp) * w;
        }
        *reinterpret_cast<float4*>(&s_part[g][8 * t])     = a0;
        *reinterpret_cast<float4*>(&s_part[g][8 * t + 4]) = a1;
    }
    __syncthreads();

    float eval = 0.f;
    if (tid < HWW) {
        #pragma unroll
        for (int gg = 0; gg < 16; ++gg) eval += s_part[gg][tid];
    }
    const int lane = tid & 31, wid = tid >> 5;

    float v = (tid < HWW) ? eval : -3.0e38f;
    #pragma unroll
    for (int o = 16; o; o >>= 1) v = fmaxf(v, __shfl_xor_sync(0xffffffffu, v, o));
    if (lane == 0) s_red[wid] = v;
    __syncthreads();
    float m = s_red[0];
    #pragma unroll
    for (int i = 1; i < 16; ++i) m = fmaxf(m, s_red[i]);

    float e = (tid < HWW) ? __expf(eval - m) : 0.f;
    float sv = e;
    #pragma unroll
    for (int o = 16; o; o >>= 1) sv += __shfl_xor_sync(0xffffffffu, sv, o);
    if (lane == 0) s_red2[wid] = sv;
    __syncthreads();
    float tot = 0.f;
    #pragma unroll
    for (int i = 0; i < 16; ++i) tot += s_red2[i];

    if (tid < HWW) {
        const float alpha = e / tot;
        g_alpha[(size_t)b * HWW + tid] = alpha;
        alphaT[(size_t)tid * BB + b] = alpha;
    }
    if (tid < EE) {
        g_xh[(size_t)b * KX + CC + tid] = __float2half_rn(emb[(size_t)b * EE + tid]);
    }
}

// ---------------------------------------------------------------------------
// Kernel 2: context GEMV. grid (8, B), 256 threads; warp per channel row.
// PDL consumer: griddepsync before reading g_alpha. Unroll 4 for deeper MLP.
// ---------------------------------------------------------------------------
__global__ __launch_bounds__(256) void ctx_kernel(const float* __restrict__ cfo)
{
    cudaGridDependencySynchronize();

    const int b  = blockIdx.y;
    const int c0 = blockIdx.x * 64;
    const int tid = threadIdx.x;
    const int lane = tid & 31, w = tid >> 5;

    __shared__ __align__(16) float s_alpha[HWW];
    if (tid < HWW) s_alpha[tid] = g_alpha[(size_t)b * HWW + tid];
    __syncthreads();

    const float4* a4 = reinterpret_cast<const float4*>(s_alpha);
    float4 aa = a4[lane];
    float4 a2 = (lane < 28) ? a4[lane + 32] : make_float4(0.f, 0.f, 0.f, 0.f);

    #pragma unroll 4
    for (int r = 0; r < 8; ++r) {
        const int c = c0 + w * 8 + r;
        const float4* rp = reinterpret_cast<const float4*>(
            cfo + ((size_t)b * CC + c) * HWW);
        float4 vv = __ldcs(rp + lane);
        float s = vv.x * aa.x + vv.y * aa.y + vv.z * aa.z + vv.w * aa.w;
        if (lane < 28) {
            float4 v2 = __ldcs(rp + lane + 32);
            s += v2.x * a2.x + v2.y * a2.y + v2.z * a2.z + v2.w * a2.w;
        }
        #pragma unroll
        for (int o = 16; o; o >>= 1) s += __shfl_xor_sync(0xffffffffu, s, o);
        if (lane == 0) {
            g_xh[(size_t)b * KX + c] = __float2half_rn(s);
        }
    }
}

// ---------------------------------------------------------------------------
// Kernel 3: gate GEMMs, fp16 MMA, split-K=4, chunk K=32, 3-stage cp.async ring
// (one barrier per chunk). PDL: gh CTAs skip griddepsync; gi CTAs sync.
// Tile 64(M) x 64(N). grid (24, 8, 8): z&1 = gemm, z>>1 = split.
// ---------------------------------------------------------------------------
#define ASTR 40   // fp16 row stride: 80 bytes

__device__ __forceinline__ void mma16816(float* c, const uint32_t* a, const uint32_t* b) {
    asm volatile(
        "mma.sync.aligned.m16n8k16.row.col.f32.f16.f16.f32 "
        "{%0,%1,%2,%3}, {%4,%5,%6,%7}, {%8,%9}, {%0,%1,%2,%3};"
        : "+f"(c[0]), "+f"(c[1]), "+f"(c[2]), "+f"(c[3])
        : "r"(a[0]), "r"(a[1]), "r"(a[2]), "r"(a[3]),
          "r"(b[0]), "r"(b[1]));
}
__device__ __forceinline__ void ldsm4(uint32_t* r, const __half* p) {
    uint32_t a = (uint32_t)__cvta_generic_to_shared(p);
    asm volatile("ldmatrix.sync.aligned.m8n8.x4.shared.b16 {%0,%1,%2,%3}, [%4];"
                 : "=r"(r[0]), "=r"(r[1]), "=r"(r[2]), "=r"(r[3]) : "r"(a));
}
__device__ __forceinline__ void cpasync16(uint32_t dst, const void* src) {
    asm volatile("cp.async.cg.shared.global [%0], [%1], 16;" :: "r"(dst), "l"(src));
}

__global__ __launch_bounds__(128) void gemm_gates()
{
    const int z      = blockIdx.z;
    const int gemmi  = z & 1;       // 0: gi (K=640), 1: gh (K=512)
    const int split  = z >> 1;      // 0..3

    // gi reads g_xh (written by ctx) -> must wait. gh reads only h/w splits.
    if (gemmi == 0) cudaGridDependencySynchronize();

    const __half* A = gemmi ? g_hh  : g_xh;
    const __half* B = gemmi ? g_whh : g_wih;
    float* outp = g_part[gemmi * 4 + split];
    const int K    = gemmi ? CC : KX;
    const int Kq   = K >> 2;        // 160 or 128
    const int koff = split * Kq;
    const int T    = Kq / 32;       // 5 or 4

    __shared__ __align__(16) __half sA[3][64 * ASTR];
    __shared__ __align__(16) __half sB[3][64 * ASTR];

    const int tid  = threadIdx.x;
    const int lane = tid & 31;
    const int wrp  = tid >> 5;
    const int warp_m = wrp >> 1;
    const int warp_n = wrp & 1;
    const int gID = lane >> 2;
    const int tig = lane & 3;
    const int m0 = blockIdx.y * 64;
    const int n0 = blockIdx.x * 64;

    const int a_rowl = lane & 15;
    const int a_kh   = (lane >> 4) * 8;
    const int b_rowl = ((lane >> 4) * 8) + (lane & 7);
    const int b_kh   = ((lane >> 3) & 1) * 8;

    const int lrow0 = tid >> 2,         lseg0 = (tid & 3) * 8;
    const int lrow1 = (tid + 128) >> 2, lseg1 = (tid & 3) * 8;

    float acc[2][4][4];
    #pragma unroll
    for (int i = 0; i < 2; ++i)
        #pragma unroll
        for (int j = 0; j < 4; ++j)
            #pragma unroll
            for (int k = 0; k < 4; ++k) acc[i][j][k] = 0.f;

    auto load_stage = [&](int s, int kt) {
        const size_t kbase = (size_t)koff + kt * 32;
        {
            size_t ga = (size_t)(m0 + lrow0) * K + kbase + lseg0;
            size_t gb = (size_t)(n0 + lrow0) * K + kbase + lseg0;
            int so = lrow0 * ASTR + lseg0;
            cpasync16((uint32_t)__cvta_generic_to_shared(&sA[s][so]), A + ga);
            cpasync16((uint32_t)__cvta_generic_to_shared(&sB[s][so]), B + gb);
        }
        {
            size_t ga = (size_t)(m0 + lrow1) * K + kbase + lseg1;
            size_t gb = (size_t)(n0 + lrow1) * K + kbase + lseg1;
            int so = lrow1 * ASTR + lseg1;
            cpasync16((uint32_t)__cvta_generic_to_shared(&sA[s][so]), A + ga);
            cpasync16((uint32_t)__cvta_generic_to_shared(&sB[s][so]), B + gb);
        }
        asm volatile("cp.async.commit_group;");
    };

    load_stage(0, 0);
    load_stage(1, 1);

    int st = 0;                      // stage of chunk t (mod 3)
    for (int t = 0; t < T; ++t) {
        if (t + 1 < T) { asm volatile("cp.async.wait_group 1;"); }
        else           { asm volatile("cp.async.wait_group 0;"); }
        __syncthreads();

        if (t + 2 < T) {
            int s2 = st + 2; if (s2 >= 3) s2 -= 3;
            load_stage(s2, t + 2);
        }

        #pragma unroll
        for (int k8 = 0; k8 < 2; ++k8) {
            const int kb = k8 * 16;
            uint32_t ah[2][4];
            #pragma unroll
            for (int m2 = 0; m2 < 2; ++m2) {
                const int r = warp_m * 32 + m2 * 16 + a_rowl;
                ldsm4(ah[m2], &sA[st][r * ASTR + kb + a_kh]);
            }
            uint32_t bh[4][2];
            #pragma unroll
            for (int p = 0; p < 2; ++p) {
                const int r = warp_n * 32 + p * 16 + b_rowl;
                uint32_t t4[4];
                ldsm4(t4, &sB[st][r * ASTR + kb + b_kh]);
                bh[2 * p][0] = t4[0]; bh[2 * p][1] = t4[1];
                bh[2 * p + 1][0] = t4[2]; bh[2 * p + 1][1] = t4[3];
            }
            #pragma unroll
            for (int m2 = 0; m2 < 2; ++m2)
                #pragma unroll
                for (int n4 = 0; n4 < 4; ++n4)
                    mma16816(acc[m2][n4], ah[m2], bh[n4]);
        }
        if (++st == 3) st = 0;
    }

    #pragma unroll
    for (int m2 = 0; m2 < 2; ++m2) {
        #pragma unroll
        for (int n4 = 0; n4 < 4; ++n4) {
            int r = m0 + warp_m * 32 + m2 * 16 + gID;
            int cb = n0 + warp_n * 32 + n4 * 8 + tig * 2;
            float2 o0 = {acc[m2][n4][0], acc[m2][n4][1]};
            float2 o1 = {acc[m2][n4][2], acc[m2][n4][3]};
            *reinterpret_cast<float2*>(outp + (size_t)r * GATES + cb) = o0;
            *reinterpret_cast<float2*>(outp + (size_t)(r + 8) * GATES + cb) = o1;
        }
    }
}

// ---------------------------------------------------------------------------
// Kernel 4: GRU combine; sums 4 split-K partials per gemm plus biases.
// PDL consumer: waits for gemm grid before reading partials.
// ---------------------------------------------------------------------------
__global__ __launch_bounds__(256) void gru_kernel(
    const float* __restrict__ h, const float* __restrict__ b_ih,
    const float* __restrict__ b_hh, float* __restrict__ out)
{
    cudaGridDependencySynchronize();

    const int i4 = blockIdx.x * 256 + threadIdx.x;
    const int b = i4 >> 7;
    const int c4 = i4 & 127;
    const size_t row = (size_t)b * GATES;

    float4 gi_r, gi_z, gi_n, gh_r, gh_z, gh_n;
    {
        const float4* bi = reinterpret_cast<const float4*>(b_ih) + c4;
        const float4* bh = reinterpret_cast<const float4*>(b_hh) + c4;
        gi_r = bi[0]; gi_z = bi[128]; gi_n = bi[256];
        gh_r = bh[0]; gh_z = bh[128]; gh_n = bh[256];
    }
    #pragma unroll
    for (int s = 0; s < 4; ++s) {
        const float4* pi = reinterpret_cast<const float4*>(g_part[s]     + row) + c4;
        const float4* pg = reinterpret_cast<const float4*>(g_part[4 + s] + row) + c4;
        float4 a = pi[0], bq = pi[128], cq = pi[256];
        float4 d = pg[0], e = pg[128],  f = pg[256];
        gi_r.x += a.x; gi_r.y += a.y; gi_r.z += a.z; gi_r.w += a.w;
        gi_z.x += bq.x; gi_z.y += bq.y; gi_z.z += bq.z; gi_z.w += bq.w;
        gi_n.x += cq.x; gi_n.y += cq.y; gi_n.z += cq.z; gi_n.w += cq.w;
        gh_r.x += d.x; gh_r.y += d.y; gh_r.z += d.z; gh_r.w += d.w;
        gh_z.x += e.x; gh_z.y += e.y; gh_z.z += e.z; gh_z.w += e.w;
        gh_n.x += f.x; gh_n.y += f.y; gh_n.z += f.z; gh_n.w += f.w;
    }

    float4 hv = reinterpret_cast<const float4*>(h)[i4];
    float4 o;
    {
        float r = sigmoid_fast(gi_r.x + gh_r.x), zz = sigmoid_fast(gi_z.x + gh_z.x);
        float n = tanh_fast(gi_n.x + r * gh_n.x);
        o.x = (1.f - zz) * n + zz * hv.x;
    }
    {
        float r = sigmoid_fast(gi_r.y + gh_r.y), zz = sigmoid_fast(gi_z.y + gh_z.y);
        float n = tanh_fast(gi_n.y + r * gh_n.y);
        o.y = (1.f - zz) * n + zz * hv.y;
    }
    {
        float r = sigmoid_fast(gi_r.z + gh_r.z), zz = sigmoid_fast(gi_z.z + gh_z.z);
        float n = tanh_fast(gi_n.z + r * gh_n.z);
        o.z = (1.f - zz) * n + zz * hv.z;
    }
    {
        float r = sigmoid_fast(gi_r.w + gh_r.w), zz = sigmoid_fast(gi_z.w + gh_z.w);
        float n = tanh_fast(gi_n.w + r * gh_n.w);
        o.w = (1.f - zz) * n + zz * hv.w;
    }
    reinterpret_cast<float4*>(out)[i4] = o;
}

// ---------------------------------------------------------------------------
static inline void launch_pdl(void* fn, dim3 grid, dim3 block, void** args) {
    cudaLaunchConfig_t cfg = {};
    cfg.gridDim  = grid;
    cfg.blockDim = block;
    cudaLaunchAttribute attr[1];
    attr[0].id = cudaLaunchAttributeProgrammaticStreamSerialization;
    attr[0].val.programmaticStreamSerializationAllowed = 1;
    cfg.attrs = attr;
    cfg.numAttrs = 1;
    cudaLaunchKernelExC(&cfg, fn, args);
}

extern "C" void kernel_launch(void* const* d_in, const int* in_sizes, int n_in,
                              void* d_out, int out_size) {
    const float* prev_hidden       = (const float*)d_in[0];
    const float* conv_feats        = (const float*)d_in[1];
    const float* conv_feats_origin = (const float*)d_in[2];
    const float* cur_embeddings    = (const float*)d_in[3];
    const float* score_w           = (const float*)d_in[4];
    const float* w_ih              = (const float*)d_in[5];
    const float* w_hh              = (const float*)d_in[6];
    const float* b_ih              = (const float*)d_in[7];
    const float* b_hh              = (const float*)d_in[8];

    float* out        = (float*)d_out;
    float* out_hidden = out;                      // [B, C]
    float* out_alphaT = out + (size_t)BB * CC;    // [HW, B]

    // split3 (triggers PDL at start -> score overlaps it fully)
    split3_kernel<<<(N1 + N2 + N3) / 1024, 256>>>(w_ih, w_hh, prev_hidden);

    // score: PDL, no griddepsync (reads pure inputs only)
    {
        void* args[] = {(void*)&prev_hidden, (void*)&conv_feats,
                        (void*)&cur_embeddings, (void*)&score_w,
                        (void*)&out_alphaT};
        launch_pdl((void*)score_kernel, dim3(BB, 1, 1), dim3(512, 1, 1), args);
    }

    // ctx: PDL + griddepsync (needs g_alpha from score)
    {
        void* args[] = {(void*)&conv_feats_origin};
        launch_pdl((void*)ctx_kernel, dim3(CC / 64, BB, 1), dim3(256, 1, 1), args);
    }

    // gemm: PDL; gh half skips sync, gi half syncs on ctx
    {
        void* args[] = {};
        launch_pdl((void*)gemm_gates, dim3(GATES / 64, BB / 64, 8),
                   dim3(128, 1, 1), args);
    }

    // gru: PDL + griddepsync
    {
        void* args[] = {(void*)&prev_hidden, (void*)&b_ih, (void*)&b_hh,
                        (void*)&out_hidden};
        launch_pdl((void*)gru_kernel, dim3((BB * CC) / 1024, 1, 1),
                   dim3(256, 1, 1), args);
    }
}

// round 17
// speedup vs baseline: 1.1519x; 1.0069x over previous
#include <cuda_runtime.h>
#include <cuda_fp16.h>
#include <cstdint>

#define BB   512
#define CC   512
#define EE   128
#define HWW  240
#define GATES 1536   // 3*C
#define KX    640    // C+E

// -------- scratch (static device arrays; no allocation allowed) -----------
// partials: index [gemm*4 + split][B*GATES]; gemm 0 = gi, 1 = gh
__device__ float g_part[8][BB * GATES];
__device__ float g_alpha[BB * HWW];

__device__ __half g_xh [BB * KX];     // fp16 x = [context, emb]
__device__ __half g_hh [BB * CC];     // fp16 prev_hidden
__device__ __half g_wih[GATES * KX];  // fp16 w_ih
__device__ __half g_whh[GATES * CC];  // fp16 w_hh

__device__ __forceinline__ float tanh_fast(float x) {
    float y; asm("tanh.approx.f32 %0, %1;" : "=f"(y) : "f"(x)); return y;
}
__device__ __forceinline__ float sigmoid_fast(float x) {
    return 0.5f * tanh_fast(0.5f * x) + 0.5f;
}

// ---------------------------------------------------------------------------
// split3: fp32 -> fp16 for w_ih, w_hh, prev_hidden; float4-wide.
// Triggers PDL immediately: score (no data dependence) launches concurrently.
// ---------------------------------------------------------------------------
#define N1 (GATES * KX)
#define N2 (GATES * CC)
#define N3 (BB * CC)

__global__ __launch_bounds__(256) void split3_kernel(
    const float* __restrict__ w_ih, const float* __restrict__ w_hh,
    const float* __restrict__ h)
{
    cudaTriggerProgrammaticLaunchCompletion();

    int i = blockIdx.x * 256 + threadIdx.x;
    const float* src; __half* dst; int off;
    if (i < N1 / 4)            { src = w_ih; dst = g_wih; off = i; }
    else if (i < (N1 + N2) / 4){ src = w_hh; dst = g_whh; off = i - N1 / 4; }
    else                       { src = h;    dst = g_hh;  off = i - (N1 + N2) / 4; }

    float4 v = reinterpret_cast<const float4*>(src)[off];
    __half2 p0 = __floats2half2_rn(v.x, v.y);
    __half2 p1 = __floats2half2_rn(v.z, v.w);
    uint2 u = {*(uint32_t*)&p0, *(uint32_t*)&p1};
    reinterpret_cast<uint2*>(dst)[off] = u;
}

// ---------------------------------------------------------------------------
// Kernel 1: score + softmax. One block per b, 512 threads.
// PDL-launched, NO griddepsync (reads pure inputs; writes disjoint from split3).
// ---------------------------------------------------------------------------
__global__ __launch_bounds__(512) void score_kernel(
    const float* __restrict__ ph,
    const float* __restrict__ cf,
    const float* __restrict__ emb,
    const float* __restrict__ sw,
    float* __restrict__ alphaT)
{
    const int b   = blockIdx.x;
    const int tid = threadIdx.x;

    __shared__ __align__(16) float s_ph[CC];
    __shared__ __align__(16) float s_sw[CC];
    __shared__ __align__(16) float s_part[16][HWW];
    __shared__ float s_red[16];
    __shared__ float s_red2[16];

    for (int i = tid; i < CC; i += 512) {
        s_ph[i] = ph[(size_t)b * CC + i];
        s_sw[i] = sw[i];
    }
    __syncthreads();

    const int g = tid >> 5;
    const int t = tid & 31;
    if (t < 30) {
        const float4* p4 = reinterpret_cast<const float4*>(
            cf + ((size_t)b * CC + g * 32) * HWW) + 2 * t;
        float4 a0 = make_float4(0.f, 0.f, 0.f, 0.f);
        float4 a1 = make_float4(0.f, 0.f, 0.f, 0.f);
        #pragma unroll 4
        for (int c = 0; c < 32; ++c) {
            float4 v0 = __ldcs(p4 + (size_t)c * 60);
            float4 v1 = __ldcs(p4 + (size_t)c * 60 + 1);
            float hp = s_ph[g * 32 + c];
            float w  = s_sw[g * 32 + c];
            a0.x += tanh_fast(v0.x + hp) * w;
            a0.y += tanh_fast(v0.y + hp) * w;
            a0.z += tanh_fast(v0.z + hp) * w;
            a0.w += tanh_fast(v0.w + hp) * w;
            a1.x += tanh_fast(v1.x + hp) * w;
            a1.y += tanh_fast(v1.y + hp) * w;
            a1.z += tanh_fast(v1.z + hp) * w;
            a1.w += tanh_fast(v1.w + hp) * w;
        }
        *reinterpret_cast<float4*>(&s_part[g][8 * t])     = a0;
        *reinterpret_cast<float4*>(&s_part[g][8 * t + 4]) = a1;
    }
    __syncthreads();

    float eval = 0.f;
    if (tid < HWW) {
        #pragma unroll
        for (int gg = 0; gg < 16; ++gg) eval += s_part[gg][tid];
    }
    const int lane = tid & 31, wid = tid >> 5;

    float v = (tid < HWW) ? eval : -3.0e38f;
    #pragma unroll
    for (int o = 16; o; o >>= 1) v = fmaxf(v, __shfl_xor_sync(0xffffffffu, v, o));
    if (lane == 0) s_red[wid] = v;
    __syncthreads();
    float m = s_red[0];
    #pragma unroll
    for (int i = 1; i < 16; ++i) m = fmaxf(m, s_red[i]);

    float e = (tid < HWW) ? __expf(eval - m) : 0.f;
    float sv = e;
    #pragma unroll
    for (int o = 16; o; o >>= 1) sv += __shfl_xor_sync(0xffffffffu, sv, o);
    if (lane == 0) s_red2[wid] = sv;
    __syncthreads();
    float tot = 0.f;
    #pragma unroll
    for (int i = 0; i < 16; ++i) tot += s_red2[i];

    if (tid < HWW) {
        const float alpha = e / tot;
        g_alpha[(size_t)b * HWW + tid] = alpha;
        alphaT[(size_t)tid * BB + b] = alpha;
    }
    if (tid < EE) {
        g_xh[(size_t)b * KX + CC + tid] = __float2half_rn(emb[(size_t)b * EE + tid]);
    }
}

// ---------------------------------------------------------------------------
// Kernel 2: context GEMV. grid (8, B), 256 threads; warp per channel row.
// PDL: griddepsync on score, then EARLY trigger so gemm (gh half) can land in
// ctx's drain tail.
// ---------------------------------------------------------------------------
__global__ __launch_bounds__(256) void ctx_kernel(const float* __restrict__ cfo)
{
    cudaGridDependencySynchronize();
    cudaTriggerProgrammaticLaunchCompletion();

    const int b  = blockIdx.y;
    const int c0 = blockIdx.x * 64;
    const int tid = threadIdx.x;
    const int lane = tid & 31, w = tid >> 5;

    __shared__ __align__(16) float s_alpha[HWW];
    if (tid < HWW) s_alpha[tid] = g_alpha[(size_t)b * HWW + tid];
    __syncthreads();

    const float4* a4 = reinterpret_cast<const float4*>(s_alpha);
    float4 aa = a4[lane];
    float4 a2 = (lane < 28) ? a4[lane + 32] : make_float4(0.f, 0.f, 0.f, 0.f);

    #pragma unroll 4
    for (int r = 0; r < 8; ++r) {
        const int c = c0 + w * 8 + r;
        const float4* rp = reinterpret_cast<const float4*>(
            cfo + ((size_t)b * CC + c) * HWW);
        float4 vv = __ldcs(rp + lane);
        float s = vv.x * aa.x + vv.y * aa.y + vv.z * aa.z + vv.w * aa.w;
        if (lane < 28) {
            float4 v2 = __ldcs(rp + lane + 32);
            s += v2.x * a2.x + v2.y * a2.y + v2.z * a2.z + v2.w * a2.w;
        }
        #pragma unroll
        for (int o = 16; o; o >>= 1) s += __shfl_xor_sync(0xffffffffu, s, o);
        if (lane == 0) {
            g_xh[(size_t)b * KX + c] = __float2half_rn(s);
        }
    }
}

// ---------------------------------------------------------------------------
// Kernel 3: gate GEMMs, fp16 MMA, split-K=4, chunk K=32, 3-stage cp.async ring.
// PDL: gh half (bids FIRST: z<4) skips griddepsync and runs in ctx's tail;
// gi half (z>=4) sleeps in griddepsync until ctx completes.
// Tile 64(M) x 64(N). grid (24, 8, 8).
// ---------------------------------------------------------------------------
#define ASTR 40   // fp16 row stride: 80 bytes

__device__ __forceinline__ void mma16816(float* c, const uint32_t* a, const uint32_t* b) {
    asm volatile(
        "mma.sync.aligned.m16n8k16.row.col.f32.f16.f16.f32 "
        "{%0,%1,%2,%3}, {%4,%5,%6,%7}, {%8,%9}, {%0,%1,%2,%3};"
        : "+f"(c[0]), "+f"(c[1]), "+f"(c[2]), "+f"(c[3])
        : "r"(a[0]), "r"(a[1]), "r"(a[2]), "r"(a[3]),
          "r"(b[0]), "r"(b[1]));
}
__device__ __forceinline__ void ldsm4(uint32_t* r, const __half* p) {
    uint32_t a = (uint32_t)__cvta_generic_to_shared(p);
    asm volatile("ldmatrix.sync.aligned.m8n8.x4.shared.b16 {%0,%1,%2,%3}, [%4];"
                 : "=r"(r[0]), "=r"(r[1]), "=r"(r[2]), "=r"(r[3]) : "r"(a));
}
__device__ __forceinline__ void cpasync16(uint32_t dst, const void* src) {
    asm volatile("cp.async.cg.shared.global [%0], [%1], 16;" :: "r"(dst), "l"(src));
}

__global__ __launch_bounds__(128) void gemm_gates()
{
    const int z      = blockIdx.z;
    const int gemmi  = (z < 4) ? 1 : 0;   // gh FIRST in bid order
    const int split  = z & 3;             // 0..3

    // gi reads g_xh (written by ctx) -> wait for ctx completion.
    // gh reads only split3 outputs -> runs immediately (in ctx's tail).
    if (gemmi == 0) cudaGridDependencySynchronize();

    const __half* A = gemmi ? g_hh  : g_xh;
    const __half* B = gemmi ? g_whh : g_wih;
    float* outp = g_part[gemmi * 4 + split];
    const int K    = gemmi ? CC : KX;
    const int Kq   = K >> 2;        // 160 or 128
    const int koff = split * Kq;
    const int T    = Kq / 32;       // 5 or 4

    __shared__ __align__(16) __half sA[3][64 * ASTR];
    __shared__ __align__(16) __half sB[3][64 * ASTR];

    const int tid  = threadIdx.x;
    const int lane = tid & 31;
    const int wrp  = tid >> 5;
    const int warp_m = wrp >> 1;
    const int warp_n = wrp & 1;
    const int gID = lane >> 2;
    const int tig = lane & 3;
    const int m0 = blockIdx.y * 64;
    const int n0 = blockIdx.x * 64;

    const int a_rowl = lane & 15;
    const int a_kh   = (lane >> 4) * 8;
    const int b_rowl = ((lane >> 4) * 8) + (lane & 7);
    const int b_kh   = ((lane >> 3) & 1) * 8;

    const int lrow0 = tid >> 2,         lseg0 = (tid & 3) * 8;
    const int lrow1 = (tid + 128) >> 2, lseg1 = (tid & 3) * 8;

    float acc[2][4][4];
    #pragma unroll
    for (int i = 0; i < 2; ++i)
        #pragma unroll
        for (int j = 0; j < 4; ++j)
            #pragma unroll
            for (int k = 0; k < 4; ++k) acc[i][j][k] = 0.f;

    auto load_stage = [&](int s, int kt) {
        const size_t kbase = (size_t)koff + kt * 32;
        {
            size_t ga = (size_t)(m0 + lrow0) * K + kbase + lseg0;
            size_t gb = (size_t)(n0 + lrow0) * K + kbase + lseg0;
            int so = lrow0 * ASTR + lseg0;
            cpasync16((uint32_t)__cvta_generic_to_shared(&sA[s][so]), A + ga);
            cpasync16((uint32_t)__cvta_generic_to_shared(&sB[s][so]), B + gb);
        }
        {
            size_t ga = (size_t)(m0 + lrow1) * K + kbase + lseg1;
            size_t gb = (size_t)(n0 + lrow1) * K + kbase + lseg1;
            int so = lrow1 * ASTR + lseg1;
            cpasync16((uint32_t)__cvta_generic_to_shared(&sA[s][so]), A + ga);
            cpasync16((uint32_t)__cvta_generic_to_shared(&sB[s][so]), B + gb);
        }
        asm volatile("cp.async.commit_group;");
    };

    load_stage(0, 0);
    load_stage(1, 1);

    int st = 0;                      // stage of chunk t (mod 3)
    for (int t = 0; t < T; ++t) {
        if (t + 1 < T) { asm volatile("cp.async.wait_group 1;"); }
        else           { asm volatile("cp.async.wait_group 0;"); }
        __syncthreads();

        if (t + 2 < T) {
            int s2 = st + 2; if (s2 >= 3) s2 -= 3;
            load_stage(s2, t + 2);
        }

        #pragma unroll
        for (int k8 = 0; k8 < 2; ++k8) {
            const int kb = k8 * 16;
            uint32_t ah[2][4];
            #pragma unroll
            for (int m2 = 0; m2 < 2; ++m2) {
                const int r = warp_m * 32 + m2 * 16 + a_rowl;
                ldsm4(ah[m2], &sA[st][r * ASTR + kb + a_kh]);
            }
            uint32_t bh[4][2];
            #pragma unroll
            for (int p = 0; p < 2; ++p) {
                const int r = warp_n * 32 + p * 16 + b_rowl;
                uint32_t t4[4];
                ldsm4(t4, &sB[st][r * ASTR + kb + b_kh]);
                bh[2 * p][0] = t4[0]; bh[2 * p][1] = t4[1];
                bh[2 * p + 1][0] = t4[2]; bh[2 * p + 1][1] = t4[3];
            }
            #pragma unroll
            for (int m2 = 0; m2 < 2; ++m2)
                #pragma unroll
                for (int n4 = 0; n4 < 4; ++n4)
                    mma16816(acc[m2][n4], ah[m2], bh[n4]);
        }
        if (++st == 3) st = 0;
    }

    #pragma unroll
    for (int m2 = 0; m2 < 2; ++m2) {
        #pragma unroll
        for (int n4 = 0; n4 < 4; ++n4) {
            int r = m0 + warp_m * 32 + m2 * 16 + gID;
            int cb = n0 + warp_n * 32 + n4 * 8 + tig * 2;
            float2 o0 = {acc[m2][n4][0], acc[m2][n4][1]};
            float2 o1 = {acc[m2][n4][2], acc[m2][n4][3]};
            *reinterpret_cast<float2*>(outp + (size_t)r * GATES + cb) = o0;
            *reinterpret_cast<float2*>(outp + (size_t)(r + 8) * GATES + cb) = o1;
        }
    }
}

// ---------------------------------------------------------------------------
// Kernel 4: GRU combine; sums 4 split-K partials per gemm plus biases.
// PDL consumer: waits for gemm grid before reading partials.
// ---------------------------------------------------------------------------
__global__ __launch_bounds__(256) void gru_kernel(
    const float* __restrict__ h, const float* __restrict__ b_ih,
    const float* __restrict__ b_hh, float* __restrict__ out)
{
    cudaGridDependencySynchronize();

    const int i4 = blockIdx.x * 256 + threadIdx.x;
    const int b = i4 >> 7;
    const int c4 = i4 & 127;
    const size_t row = (size_t)b * GATES;

    float4 gi_r, gi_z, gi_n, gh_r, gh_z, gh_n;
    {
        const float4* bi = reinterpret_cast<const float4*>(b_ih) + c4;
        const float4* bh = reinterpret_cast<const float4*>(b_hh) + c4;
        gi_r = bi[0]; gi_z = bi[128]; gi_n = bi[256];
        gh_r = bh[0]; gh_z = bh[128]; gh_n = bh[256];
    }
    #pragma unroll
    for (int s = 0; s < 4; ++s) {
        const float4* pi = reinterpret_cast<const float4*>(g_part[s]     + row) + c4;
        const float4* pg = reinterpret_cast<const float4*>(g_part[4 + s] + row) + c4;
        float4 a = pi[0], bq = pi[128], cq = pi[256];
        float4 d = pg[0], e = pg[128],  f = pg[256];
        gi_r.x += a.x; gi_r.y += a.y; gi_r.z += a.z; gi_r.w += a.w;
        gi_z.x += bq.x; gi_z.y += bq.y; gi_z.z += bq.z; gi_z.w += bq.w;
        gi_n.x += cq.x; gi_n.y += cq.y; gi_n.z += cq.z; gi_n.w += cq.w;
        gh_r.x += d.x; gh_r.y += d.y; gh_r.z += d.z; gh_r.w += d.w;
        gh_z.x += e.x; gh_z.y += e.y; gh_z.z += e.z; gh_z.w += e.w;
        gh_n.x += f.x; gh_n.y += f.y; gh_n.z += f.z; gh_n.w += f.w;
    }

    float4 hv = reinterpret_cast<const float4*>(h)[i4];
    float4 o;
    {
        float r = sigmoid_fast(gi_r.x + gh_r.x), zz = sigmoid_fast(gi_z.x + gh_z.x);
        float n = tanh_fast(gi_n.x + r * gh_n.x);
        o.x = (1.f - zz) * n + zz * hv.x;
    }
    {
        float r = sigmoid_fast(gi_r.y + gh_r.y), zz = sigmoid_fast(gi_z.y + gh_z.y);
        float n = tanh_fast(gi_n.y + r * gh_n.y);
        o.y = (1.f - zz) * n + zz * hv.y;
    }
    {
        float r = sigmoid_fast(gi_r.z + gh_r.z), zz = sigmoid_fast(gi_z.z + gh_z.z);
        float n = tanh_fast(gi_n.z + r * gh_n.z);
        o.z = (1.f - zz) * n + zz * hv.z;
    }
    {
        float r = sigmoid_fast(gi_r.w + gh_r.w), zz = sigmoid_fast(gi_z.w + gh_z.w);
        float n = tanh_fast(gi_n.w + r * gh_n.w);
        o.w = (1.f - zz) * n + zz * hv.w;
    }
    reinterpret_cast<float4*>(out)[i4] = o;
}

// ---------------------------------------------------------------------------
static inline void launch_pdl(void* fn, dim3 grid, dim3 block, void** args) {
    cudaLaunchConfig_t cfg = {};
    cfg.gridDim  = grid;
    cfg.blockDim = block;
    cudaLaunchAttribute attr[1];
    attr[0].id = cudaLaunchAttributeProgrammaticStreamSerialization;
    attr[0].val.programmaticStreamSerializationAllowed = 1;
    cfg.attrs = attr;
    cfg.numAttrs = 1;
    cudaLaunchKernelExC(&cfg, fn, args);
}

extern "C" void kernel_launch(void* const* d_in, const int* in_sizes, int n_in,
                              void* d_out, int out_size) {
    const float* prev_hidden       = (const float*)d_in[0];
    const float* conv_feats        = (const float*)d_in[1];
    const float* conv_feats_origin = (const float*)d_in[2];
    const float* cur_embeddings    = (const float*)d_in[3];
    const float* score_w           = (const float*)d_in[4];
    const float* w_ih              = (const float*)d_in[5];
    const float* w_hh              = (const float*)d_in[6];
    const float* b_ih              = (const float*)d_in[7];
    const float* b_hh              = (const float*)d_in[8];

    float* out        = (float*)d_out;
    float* out_hidden = out;                      // [B, C]
    float* out_alphaT = out + (size_t)BB * CC;    // [HW, B]

    // split3 (triggers PDL at start -> score overlaps it fully)
    split3_kernel<<<(N1 + N2 + N3) / 1024, 256>>>(w_ih, w_hh, prev_hidden);

    // score: PDL, no griddepsync (reads pure inputs only)
    {
        void* args[] = {(void*)&prev_hidden, (void*)&conv_feats,
                        (void*)&cur_embeddings, (void*)&score_w,
                        (void*)&out_alphaT};
        launch_pdl((void*)score_kernel, dim3(BB, 1, 1), dim3(512, 1, 1), args);
    }

    // ctx: PDL + griddepsync (needs g_alpha), then triggers early for gemm
    {
        void* args[] = {(void*)&conv_feats_origin};
        launch_pdl((void*)ctx_kernel, dim3(CC / 64, BB, 1), dim3(256, 1, 1), args);
    }

    // gemm: PDL; gh half (first in bid order) runs in ctx tail, gi half syncs
    {
        void* args[] = {};
        launch_pdl((void*)gemm_gates, dim3(GATES / 64, BB / 64, 8),
                   dim3(128, 1, 1), args);
    }

    // gru: PDL + griddepsync
    {
        void* args[] = {(void*)&prev_hidden, (void*)&b_ih, (void*)&b_hh,
                        (void*)&out_hidden};
        launch_pdl((void*)gru_kernel, dim3((BB * CC) / 1024, 1, 1),
                   dim3(256, 1, 1), args);
    }
}